// round 12
// baseline (speedup 1.0000x reference)
#include <cuda_runtime.h>
#include <cfloat>
#include <cstdint>

#define Nn 100000
#define NnP 100096          // multiple of 128 (MMA tile)
#define Ee 1600000
#define Dd 64
#define Gg 512
#define OUTD 16
#define NL 5
#define DELTA 2.5749f
#define BN_EPS 1e-5f
#define NBMMA (NnP / 128)   // 782

// ---------------- static device scratch ----------------
static __device__ float g_h0[NnP * Dd];        // ping-pong node features
static __device__ float g_h1[NnP * Dd];
static __device__ float g_cfac[NnP];
static __device__ int   g_deg[Nn];
static __device__ int   g_sc[Nn];
static __device__ int   g_bsum[128];
static __device__ int   g_rowptr[Nn + 1];
static __device__ int   g_cursor[Nn];
static __device__ int   g_esrc[Ee];
static __device__ float g_part[NBMMA * 128];   // per-CTA BN partials
static __device__ float g_scale[Dd];
static __device__ float g_shift[Dd];
static __device__ int   g_bstart[Gg + 1];
static __device__ float g_gpool[Gg * Dd];
static __device__ float g_encWt[Dd * Dd];
static __device__ float g_nnW1h[NL * Dd * Dd];  // [k][d] tf32 hi
static __device__ float g_nnW1l[NL * Dd * Dd];
static __device__ float g_nnW2h[NL * Dd * Dd];
static __device__ float g_nnW2l[NL * Dd * Dd];
static __device__ float g_mlpBh[NL * 256 * 192];  // [k][n], tf32 hi
static __device__ float g_mlpBl[NL * 256 * 192];
static __device__ float g_fc1Wt[Dd * Dd];
static __device__ float g_fc2Wt[Dd * OUTD];

__device__ __forceinline__ float tf32r(float x) {
    float y;
    asm("cvt.rna.tf32.f32 %0, %1;" : "=f"(y) : "f"(x));
    return y;
}
__device__ __forceinline__ void mma1688(float* c, const uint32_t* a, uint32_t b0, uint32_t b1) {
    asm volatile(
        "mma.sync.aligned.m16n8k8.row.col.f32.tf32.tf32.f32 "
        "{%0,%1,%2,%3}, {%4,%5,%6,%7}, {%8,%9}, {%0,%1,%2,%3};"
        : "+f"(c[0]), "+f"(c[1]), "+f"(c[2]), "+f"(c[3])
        : "r"(a[0]), "r"(a[1]), "r"(a[2]), "r"(a[3]), "r"(b0), "r"(b1));
}
__device__ __forceinline__ uint32_t smem_u32(const void* p) {
    uint32_t a;
    asm("{ .reg .u64 t; cvta.to.shared.u64 t, %1; cvt.u32.u64 %0, t; }" : "=r"(a) : "l"(p));
    return a;
}
__device__ __forceinline__ void cp16(uint32_t d, const void* s) {
    asm volatile("cp.async.cg.shared.global [%0], [%1], 16;" :: "r"(d), "l"(s));
}
#define CP_COMMIT() asm volatile("cp.async.commit_group;" ::: "memory")
#define CP_WAIT(n)  asm volatile("cp.async.wait_group %0;" :: "n"(n) : "memory")

// ---------------- CSR build ----------------
__global__ void k_zero_deg() {
    int i = blockIdx.x * blockDim.x + threadIdx.x;
    if (i < Nn) g_deg[i] = 0;
}
__global__ void k_count(const int* __restrict__ dst) {
    int e = blockIdx.x * blockDim.x + threadIdx.x;
    if (e < Ee) atomicAdd(&g_deg[dst[e]], 1);
}
__global__ void k_scan_block() {
    __shared__ int sm[1024];
    int i = blockIdx.x * 1024 + threadIdx.x;
    int v = (i < Nn) ? g_deg[i] : 0;
    sm[threadIdx.x] = v;
    __syncthreads();
    for (int off = 1; off < 1024; off <<= 1) {
        int t = 0;
        if (threadIdx.x >= off) t = sm[threadIdx.x - off];
        __syncthreads();
        sm[threadIdx.x] += t;
        __syncthreads();
    }
    if (i < Nn) g_sc[i] = sm[threadIdx.x];
    if (threadIdx.x == 1023) g_bsum[blockIdx.x] = sm[1023];
}
// parallel exclusive scan over block sums (nb <= 128)
__global__ void k_scan_tops(int nb) {
    __shared__ int sm2[128];
    int t = threadIdx.x;
    int v = (t < nb) ? g_bsum[t] : 0;
    sm2[t] = v;
    __syncthreads();
    for (int off = 1; off < 128; off <<= 1) {
        int u = (t >= off) ? sm2[t - off] : 0;
        __syncthreads();
        sm2[t] += u;
        __syncthreads();
    }
    if (t < nb) g_bsum[t] = sm2[t] - v;
}
__global__ void k_rowptr() {
    int i = blockIdx.x * blockDim.x + threadIdx.x;
    if (i < Nn) {
        int rp = g_sc[i] - g_deg[i] + g_bsum[i >> 10];
        g_rowptr[i] = rp;
        g_cursor[i] = rp;
        g_cfac[i] = fmaxf((float)g_deg[i], 1.0f);
    }
    if (i == 0) g_rowptr[Nn] = Ee;
}
__global__ void k_scatter(const int* __restrict__ src, const int* __restrict__ dst) {
    int e = blockIdx.x * blockDim.x + threadIdx.x;
    if (e < Ee) {
        int p = atomicAdd(&g_cursor[dst[e]], 1);
        g_esrc[p] = src[e];
    }
}
__global__ void k_sortrows() {
    int n = blockIdx.x * blockDim.x + threadIdx.x;
    if (n >= Nn) return;
    int beg = g_rowptr[n], end = g_rowptr[n + 1];
    int deg = end - beg;
    if (deg <= 1) return;
    if (deg <= 64) {
        int buf[64];
        for (int i = 0; i < deg; i++) buf[i] = g_esrc[beg + i];
        for (int i = 1; i < deg; i++) {
            int v = buf[i];
            int j = i - 1;
            while (j >= 0 && buf[j] > v) { buf[j + 1] = buf[j]; j--; }
            buf[j + 1] = v;
        }
        for (int i = 0; i < deg; i++) g_esrc[beg + i] = buf[i];
    } else {
        for (int i = beg + 1; i < end; i++) {
            int v = g_esrc[i];
            int j = i - 1;
            while (j >= beg && g_esrc[j] > v) { g_esrc[j + 1] = g_esrc[j]; j--; }
            g_esrc[j + 1] = v;
        }
    }
}

// ---------------- weight prep ----------------
__global__ void k_t64(const float* __restrict__ W, float* __restrict__ Wt, int nm) {
    int idx = blockIdx.x * blockDim.x + threadIdx.x;
    if (idx >= nm * 4096) return;
    int m = idx >> 12, r = idx & 4095;
    int d = r >> 6, k = r & 63;
    Wt[(m << 12) + (k << 6) + d] = W[idx];
}
__global__ void k_t64split(const float* __restrict__ W, float* __restrict__ Wh,
                           float* __restrict__ Wl, int nm) {
    int idx = blockIdx.x * blockDim.x + threadIdx.x;
    if (idx >= nm * 4096) return;
    int m = idx >> 12, r = idx & 4095;
    int d = r >> 6, k = r & 63;
    float w = W[idx];
    float h = tf32r(w);
    Wh[(m << 12) + (k << 6) + d] = h;
    Wl[(m << 12) + (k << 6) + d] = tf32r(w - h);
}
__global__ void k_tmlpB(const float* __restrict__ W) {
    int idx = blockIdx.x * blockDim.x + threadIdx.x;
    if (idx >= NL * 256 * 192) return;
    int m = idx / 49152, r = idx % 49152;
    int k = r / 192, n = r % 192;
    int d = n & 63, b = n >> 6;
    float w = W[m * 49152 + d * 768 + b * 256 + k];
    float h = tf32r(w);
    g_mlpBh[idx] = h;
    g_mlpBl[idx] = tf32r(w - h);
}
// also initializes identity affine for layer 0
__global__ void k_tfc2(const float* __restrict__ W) {
    int idx = blockIdx.x * blockDim.x + threadIdx.x;
    if (idx < 64) { g_scale[idx] = 1.0f; g_shift[idx] = 0.0f; }
    if (idx >= Dd * OUTD) return;
    int o = idx >> 6, k = idx & 63;
    g_fc2Wt[k * 16 + o] = W[idx];
}

// ---------------- 64x64 linear (encoder only) ----------------
template <bool RELU>
__global__ void __launch_bounds__(64) k_lin64(const float* __restrict__ A,
                                              const float* __restrict__ Wt,
                                              const float* __restrict__ b,
                                              float* __restrict__ C) {
    __shared__ float4 Asm[64][16];
    int row0 = blockIdx.x * 64, tid = threadIdx.x;
    for (int t = tid; t < 1024; t += 64) {
        int r = t >> 4, c = t & 15;
        float4 v = make_float4(0.f, 0.f, 0.f, 0.f);
        if (row0 + r < Nn) v = ((const float4*)A)[(row0 + r) * 16 + c];
        Asm[r][c] = v;
    }
    __syncthreads();
    float acc[64];
#pragma unroll
    for (int r = 0; r < 64; r++) acc[r] = 0.f;
#pragma unroll 1
    for (int k4 = 0; k4 < 16; k4++) {
        float w0 = Wt[(k4 * 4 + 0) * 64 + tid];
        float w1 = Wt[(k4 * 4 + 1) * 64 + tid];
        float w2 = Wt[(k4 * 4 + 2) * 64 + tid];
        float w3 = Wt[(k4 * 4 + 3) * 64 + tid];
#pragma unroll
        for (int r = 0; r < 64; r++) {
            float4 a = Asm[r][k4];
            float t0 = fmaf(a.x, w0, acc[r]);
            t0 = fmaf(a.y, w1, t0);
            t0 = fmaf(a.z, w2, t0);
            acc[r] = fmaf(a.w, w3, t0);
        }
    }
    float bb = b[tid];
    for (int r = 0; r < 64; r++) {
        if (row0 + r < Nn) {
            float v = acc[r] + bb;
            if (RELU) v = fmaxf(v, 0.f);
            C[(row0 + r) * 64 + tid] = v;
        }
    }
}

// ---------------- fully fused layer kernel (ping-pong h: read hin, write hout) ----------------
// phase 0: gather + PNA stats for this CTA's 128 rows -> smem baseF (fp32)
// phase 1: pipelined 3xTF32 GEMM S = base @ B, A split hi/lo at fragment load
// phase 2: stage S + prefetch W1; combine -> nn A fragments (smem)
// phase 3: nn stage1/stage2 (warps 0-7), W2 prefetched under resplit
// phase 4: epilogue writes hout + deterministic BN partials
#define BF_STRIDE 260
#define BSTG_OFF 33280
#define BSTG_HALF 3200
#define BSTG_SZ 6400
#define BS_STRIDE 200
#define SS_STRIDE 200
#define FA_STRIDE 68
#define FW_STRIDE 72
#define L_ASH 25600
#define L_ASL (L_ASH + 128 * FA_STRIDE)     // 34304
#define L_WH  (L_ASL + 128 * FA_STRIDE)     // 43008
#define L_WL  (L_WH + 64 * FW_STRIDE)       // 47616
#define L_SMEM_FLOATS (L_WL + 64 * FW_STRIDE)  // 52224
#define L_SMEM_BYTES (L_SMEM_FLOATS * 4)       // 208896

__global__ void __launch_bounds__(384)
k_layer(const float* __restrict__ hin, float* __restrict__ hout,
        const float* __restrict__ Bh, const float* __restrict__ Bl,
        const float* __restrict__ mb,
        const float* __restrict__ W1h, const float* __restrict__ W1l,
        const float* __restrict__ W2h, const float* __restrict__ W2l,
        const float* __restrict__ b1, const float* __restrict__ b2) {
    extern __shared__ float sm[];
    uint32_t sb = smem_u32(sm);
    int tid = threadIdx.x, wid = tid >> 5, lane = tid & 31;
    int gid = lane >> 2, tig = lane & 3;
    int row0 = blockIdx.x * 128;
    int mrow0 = (wid & 3) * 32;
    int ncol0p = (wid >> 2) * 64;   // pna n offset (12 warps: 4m x 3n)
    int ncol0f = (wid >> 2) * 32;   // nn n offset (warps 0-7: 4m x 2n)

    auto load_B = [&](int kc, int s) {
        uint32_t bH = sb + (uint32_t)(BSTG_OFF + s * BSTG_SZ) * 4;
        uint32_t bL = bH + BSTG_HALF * 4;
        for (int i = tid; i < 768; i += 384) {
            int r = i / 48, c4 = i % 48;
            uint32_t off = (uint32_t)(r * BS_STRIDE + c4 * 4) * 4;
            size_t go = (size_t)(kc * 16 + r) * 192 + c4 * 4;
            cp16(bH + off, &Bh[go]);
            cp16(bL + off, &Bl[go]);
        }
    };

    // prefetch B chunks 0 and 1 (hidden under gather)
    load_B(0, 0);
    CP_COMMIT();
    load_B(1, 1);
    CP_COMMIT();

    // ---- phase 0: gather (warp per node, affine on the fly) ----
    {
        const float2* hp = (const float2*)hin;
        float scx = g_scale[2 * lane], scy = g_scale[2 * lane + 1];
        float shx = g_shift[2 * lane], shy = g_shift[2 * lane + 1];
        for (int nloc = wid; nloc < 128; nloc += 12) {
            int w = row0 + nloc;
            float* bp = sm + nloc * BF_STRIDE;
            if (w >= Nn) {
                for (int c = lane; c < 128; c += 32) {
                    bp[2 * c] = 0.f;
                    bp[2 * c + 1] = 0.f;
                }
                continue;
            }
            int beg = g_rowptr[w], end = g_rowptr[w + 1];
            float sxA = 0.f, syA = 0.f, qxA = 0.f, qyA = 0.f;
            float sxB = 0.f, syB = 0.f, qxB = 0.f, qyB = 0.f;
            float mxx = -FLT_MAX, mxy = -FLT_MAX;
            int j = beg;
            for (; j + 3 < end; j += 4) {
                int s0 = g_esrc[j];
                int s1 = g_esrc[j + 1];
                int s2 = g_esrc[j + 2];
                int s3 = g_esrc[j + 3];
                float2 r0 = hp[s0 * 32 + lane];
                float2 r1 = hp[s1 * 32 + lane];
                float2 r2 = hp[s2 * 32 + lane];
                float2 r3 = hp[s3 * 32 + lane];
                float v0x = fmaf(r0.x, scx, shx), v0y = fmaf(r0.y, scy, shy);
                float v1x = fmaf(r1.x, scx, shx), v1y = fmaf(r1.y, scy, shy);
                float v2x = fmaf(r2.x, scx, shx), v2y = fmaf(r2.y, scy, shy);
                float v3x = fmaf(r3.x, scx, shx), v3y = fmaf(r3.y, scy, shy);
                sxA += v0x; syA += v0y;
                qxA = fmaf(v0x, v0x, qxA); qyA = fmaf(v0y, v0y, qyA);
                mxx = fmaxf(mxx, v0x); mxy = fmaxf(mxy, v0y);
                sxB += v1x; syB += v1y;
                qxB = fmaf(v1x, v1x, qxB); qyB = fmaf(v1y, v1y, qyB);
                mxx = fmaxf(mxx, v1x); mxy = fmaxf(mxy, v1y);
                sxA += v2x; syA += v2y;
                qxA = fmaf(v2x, v2x, qxA); qyA = fmaf(v2y, v2y, qyA);
                mxx = fmaxf(mxx, v2x); mxy = fmaxf(mxy, v2y);
                sxB += v3x; syB += v3y;
                qxB = fmaf(v3x, v3x, qxB); qyB = fmaf(v3y, v3y, qyB);
                mxx = fmaxf(mxx, v3x); mxy = fmaxf(mxy, v3y);
            }
            for (; j < end; j++) {
                int s0 = g_esrc[j];
                float2 r0 = hp[s0 * 32 + lane];
                float v0x = fmaf(r0.x, scx, shx), v0y = fmaf(r0.y, scy, shy);
                sxA += v0x; syA += v0y;
                qxA = fmaf(v0x, v0x, qxA); qyA = fmaf(v0y, v0y, qyA);
                mxx = fmaxf(mxx, v0x); mxy = fmaxf(mxy, v0y);
            }
            float sx = sxA + sxB, sy = syA + syB;
            float qx = qxA + qxB, qy = qyA + qyB;
            if (end == beg) { mxx = 0.f; mxy = 0.f; }
            float c = g_cfac[w];
            float inv = 1.f / c;
            float mex = sx * inv, mey = sy * inv;
            float vx = fmaxf(qx * inv - mex * mex, 0.f);
            float vy = fmaxf(qy * inv - mey * mey, 0.f);
            bp[2 * lane] = sx;        bp[2 * lane + 1] = sy;
            bp[64 + 2 * lane] = mxx;  bp[64 + 2 * lane + 1] = mxy;
            bp[128 + 2 * lane] = mex; bp[128 + 2 * lane + 1] = mey;
            bp[192 + 2 * lane] = vx;  bp[192 + 2 * lane + 1] = vy;
        }
    }

    // ---- phase 1: pipelined GEMM (16 chunks of K=16) ----
    float acc[2][8][4];
#pragma unroll
    for (int mt = 0; mt < 2; mt++)
#pragma unroll
        for (int nt = 0; nt < 8; nt++)
#pragma unroll
            for (int j = 0; j < 4; j++) acc[mt][nt][j] = 0.f;

#pragma unroll 1
    for (int kc = 0; kc < 16; kc++) {
        if (kc == 15) { CP_WAIT(0); } else { CP_WAIT(1); }
        __syncthreads();
        const float* BsH = sm + BSTG_OFF + (kc & 1) * BSTG_SZ;
        const float* BsL = BsH + BSTG_HALF;
#pragma unroll
        for (int k8 = 0; k8 < 2; k8++) {
            int acol = kc * 16 + k8 * 8 + tig;
            int brow = k8 * 8 + tig;
            uint32_t ah[2][4], al[2][4];
#pragma unroll
            for (int mt = 0; mt < 2; mt++) {
                int mr = mrow0 + mt * 16 + gid;
                float a0 = sm[mr * BF_STRIDE + acol];
                float a1 = sm[(mr + 8) * BF_STRIDE + acol];
                float a2 = sm[mr * BF_STRIDE + acol + 4];
                float a3 = sm[(mr + 8) * BF_STRIDE + acol + 4];
                float h0 = tf32r(a0), h1 = tf32r(a1), h2 = tf32r(a2), h3 = tf32r(a3);
                ah[mt][0] = __float_as_uint(h0);
                ah[mt][1] = __float_as_uint(h1);
                ah[mt][2] = __float_as_uint(h2);
                ah[mt][3] = __float_as_uint(h3);
                al[mt][0] = __float_as_uint(tf32r(a0 - h0));
                al[mt][1] = __float_as_uint(tf32r(a1 - h1));
                al[mt][2] = __float_as_uint(tf32r(a2 - h2));
                al[mt][3] = __float_as_uint(tf32r(a3 - h3));
            }
#pragma unroll
            for (int nt = 0; nt < 8; nt++) {
                int nc = ncol0p + nt * 8 + gid;
                uint32_t bh0 = __float_as_uint(BsH[brow * BS_STRIDE + nc]);
                uint32_t bh1 = __float_as_uint(BsH[(brow + 4) * BS_STRIDE + nc]);
                uint32_t bl0 = __float_as_uint(BsL[brow * BS_STRIDE + nc]);
                uint32_t bl1 = __float_as_uint(BsL[(brow + 4) * BS_STRIDE + nc]);
                mma1688(acc[0][nt], ah[0], bh0, bh1);
                mma1688(acc[0][nt], ah[0], bl0, bl1);
                mma1688(acc[0][nt], al[0], bh0, bh1);
                mma1688(acc[1][nt], ah[1], bh0, bh1);
                mma1688(acc[1][nt], ah[1], bl0, bl1);
                mma1688(acc[1][nt], al[1], bh0, bh1);
            }
        }
        __syncthreads();
        if (kc + 2 < 16) {
            load_B(kc + 2, kc & 1);
            CP_COMMIT();
        }
    }

    // ---- phase 2: prefetch W1, stage S, combine -> nn fragments ----
    {
        uint32_t whA = sb + L_WH * 4, wlA = sb + L_WL * 4;
        for (int i = tid; i < 2048; i += 384) {
            int c = i & 1023;
            int k = c >> 4, c4 = c & 15;
            uint32_t off = (uint32_t)(k * FW_STRIDE + c4 * 4) * 4;
            if (i < 1024) cp16(whA + off, &W1h[c * 4]);
            else          cp16(wlA + off, &W1l[c * 4]);
        }
        CP_COMMIT();
    }
#pragma unroll
    for (int mt = 0; mt < 2; mt++) {
#pragma unroll
        for (int nt = 0; nt < 8; nt++) {
            int r = mrow0 + mt * 16 + gid;
            int c = ncol0p + nt * 8 + tig * 2;
            *(float2*)&sm[r * SS_STRIDE + c] = make_float2(acc[mt][nt][0], acc[mt][nt][1]);
            *(float2*)&sm[(r + 8) * SS_STRIDE + c] = make_float2(acc[mt][nt][2], acc[mt][nt][3]);
        }
    }
    __syncthreads();

    // combine: u = affine(hin) + mb + S0 + (c/D)S1 + (D/c)S2 -> split into frags
    {
        float* Af = sm + L_ASH;
        float* Al = sm + L_ASL;
        for (int i = tid; i < 128 * 64; i += 384) {
            int r = i >> 6, d = i & 63;
            int row = row0 + r;
            float h = 0.f, l = 0.f;
            if (row < Nn) {
                float cf = g_cfac[row];
                float aa = cf * (1.0f / DELTA);
                float b2c = DELTA / cf;
                const float* Sr = sm + r * SS_STRIDE;
                float x = fmaf(hin[(size_t)row * 64 + d], g_scale[d], g_shift[d]);
                float v = x + mb[d] + Sr[d] + aa * Sr[64 + d] + b2c * Sr[128 + d];
                h = tf32r(v);
                l = tf32r(v - h);
            }
            Af[r * FA_STRIDE + d] = h;
            Al[r * FA_STRIDE + d] = l;
        }
    }
    CP_WAIT(0);
    __syncthreads();

    // ---- phase 3: nn stage 1 (warps 0-7) ----
    float acc2[2][4][4];
    const float* Af = sm + L_ASH;
    const float* Al = sm + L_ASL;
    const float* wh = sm + L_WH;
    const float* wl = sm + L_WL;
    if (wid < 8) {
#pragma unroll
        for (int mt = 0; mt < 2; mt++)
#pragma unroll
            for (int nt = 0; nt < 4; nt++)
#pragma unroll
                for (int j = 0; j < 4; j++) acc2[mt][nt][j] = 0.f;
#pragma unroll 1
        for (int k8 = 0; k8 < 8; k8++) {
            int kb = k8 * 8;
            uint32_t ah[2][4], al2[2][4];
#pragma unroll
            for (int mt = 0; mt < 2; mt++) {
                int mr = mrow0 + mt * 16 + gid;
                ah[mt][0] = __float_as_uint(Af[mr * FA_STRIDE + kb + tig]);
                ah[mt][1] = __float_as_uint(Af[(mr + 8) * FA_STRIDE + kb + tig]);
                ah[mt][2] = __float_as_uint(Af[mr * FA_STRIDE + kb + tig + 4]);
                ah[mt][3] = __float_as_uint(Af[(mr + 8) * FA_STRIDE + kb + tig + 4]);
                al2[mt][0] = __float_as_uint(Al[mr * FA_STRIDE + kb + tig]);
                al2[mt][1] = __float_as_uint(Al[(mr + 8) * FA_STRIDE + kb + tig]);
                al2[mt][2] = __float_as_uint(Al[mr * FA_STRIDE + kb + tig + 4]);
                al2[mt][3] = __float_as_uint(Al[(mr + 8) * FA_STRIDE + kb + tig + 4]);
            }
#pragma unroll
            for (int nt = 0; nt < 4; nt++) {
                int nc = ncol0f + nt * 8 + gid;
                uint32_t bh0 = __float_as_uint(wh[(kb + tig) * FW_STRIDE + nc]);
                uint32_t bh1 = __float_as_uint(wh[(kb + tig + 4) * FW_STRIDE + nc]);
                uint32_t bl0 = __float_as_uint(wl[(kb + tig) * FW_STRIDE + nc]);
                uint32_t bl1 = __float_as_uint(wl[(kb + tig + 4) * FW_STRIDE + nc]);
                mma1688(acc2[0][nt], ah[0], bh0, bh1);
                mma1688(acc2[0][nt], ah[0], bl0, bl1);
                mma1688(acc2[0][nt], al2[0], bh0, bh1);
                mma1688(acc2[1][nt], ah[1], bh0, bh1);
                mma1688(acc2[1][nt], ah[1], bl0, bl1);
                mma1688(acc2[1][nt], al2[1], bh0, bh1);
            }
        }
    }
    __syncthreads();   // all reads of W1 + A fragments done

    // async load W2 into same weight buffer; hide under relu-resplit
    {
        uint32_t whA = sb + L_WH * 4, wlA = sb + L_WL * 4;
        for (int i = tid; i < 2048; i += 384) {
            int c = i & 1023;
            int k = c >> 4, c4 = c & 15;
            uint32_t off = (uint32_t)(k * FW_STRIDE + c4 * 4) * 4;
            if (i < 1024) cp16(whA + off, &W2h[c * 4]);
            else          cp16(wlA + off, &W2l[c * 4]);
        }
        CP_COMMIT();
    }
    // relu + bias, re-split into A fragments
    if (wid < 8) {
        float* Afw = sm + L_ASH;
        float* Alw = sm + L_ASL;
#pragma unroll
        for (int mt = 0; mt < 2; mt++) {
#pragma unroll
            for (int nt = 0; nt < 4; nt++) {
                int r = mrow0 + mt * 16 + gid;
                int c = ncol0f + nt * 8 + tig * 2;
                float bb0 = b1[c], bb1 = b1[c + 1];
                float u0 = fmaxf(acc2[mt][nt][0] + bb0, 0.f);
                float u1 = fmaxf(acc2[mt][nt][1] + bb1, 0.f);
                float u2 = fmaxf(acc2[mt][nt][2] + bb0, 0.f);
                float u3 = fmaxf(acc2[mt][nt][3] + bb1, 0.f);
                float h0 = tf32r(u0), h1 = tf32r(u1), h2 = tf32r(u2), h3 = tf32r(u3);
                Afw[r * FA_STRIDE + c] = h0;
                Afw[r * FA_STRIDE + c + 1] = h1;
                Afw[(r + 8) * FA_STRIDE + c] = h2;
                Afw[(r + 8) * FA_STRIDE + c + 1] = h3;
                Alw[r * FA_STRIDE + c] = tf32r(u0 - h0);
                Alw[r * FA_STRIDE + c + 1] = tf32r(u1 - h1);
                Alw[(r + 8) * FA_STRIDE + c] = tf32r(u2 - h2);
                Alw[(r + 8) * FA_STRIDE + c + 1] = tf32r(u3 - h3);
            }
        }
    }
    CP_WAIT(0);
    __syncthreads();

    // ---- nn stage 2 ----
    if (wid < 8) {
#pragma unroll
        for (int mt = 0; mt < 2; mt++)
#pragma unroll
            for (int nt = 0; nt < 4; nt++)
#pragma unroll
                for (int j = 0; j < 4; j++) acc2[mt][nt][j] = 0.f;
#pragma unroll 1
        for (int k8 = 0; k8 < 8; k8++) {
            int kb = k8 * 8;
            uint32_t ah[2][4], al2[2][4];
#pragma unroll
            for (int mt = 0; mt < 2; mt++) {
                int mr = mrow0 + mt * 16 + gid;
                ah[mt][0] = __float_as_uint(Af[mr * FA_STRIDE + kb + tig]);
                ah[mt][1] = __float_as_uint(Af[(mr + 8) * FA_STRIDE + kb + tig]);
                ah[mt][2] = __float_as_uint(Af[mr * FA_STRIDE + kb + tig + 4]);
                ah[mt][3] = __float_as_uint(Af[(mr + 8) * FA_STRIDE + kb + tig + 4]);
                al2[mt][0] = __float_as_uint(Al[mr * FA_STRIDE + kb + tig]);
                al2[mt][1] = __float_as_uint(Al[(mr + 8) * FA_STRIDE + kb + tig]);
                al2[mt][2] = __float_as_uint(Al[mr * FA_STRIDE + kb + tig + 4]);
                al2[mt][3] = __float_as_uint(Al[(mr + 8) * FA_STRIDE + kb + tig + 4]);
            }
#pragma unroll
            for (int nt = 0; nt < 4; nt++) {
                int nc = ncol0f + nt * 8 + gid;
                uint32_t bh0 = __float_as_uint(wh[(kb + tig) * FW_STRIDE + nc]);
                uint32_t bh1 = __float_as_uint(wh[(kb + tig + 4) * FW_STRIDE + nc]);
                uint32_t bl0 = __float_as_uint(wl[(kb + tig) * FW_STRIDE + nc]);
                uint32_t bl1 = __float_as_uint(wl[(kb + tig + 4) * FW_STRIDE + nc]);
                mma1688(acc2[0][nt], ah[0], bh0, bh1);
                mma1688(acc2[0][nt], ah[0], bl0, bl1);
                mma1688(acc2[0][nt], al2[0], bh0, bh1);
                mma1688(acc2[1][nt], ah[1], bh0, bh1);
                mma1688(acc2[1][nt], ah[1], bl0, bl1);
                mma1688(acc2[1][nt], al2[1], bh0, bh1);
            }
        }
    }
    __syncthreads();   // A fragments free for output staging

    // ---- phase 4: epilogue (outer relu) + BN staging ----
    if (wid < 8) {
        float* Afw = sm + L_ASH;
#pragma unroll
        for (int mt = 0; mt < 2; mt++) {
#pragma unroll
            for (int nt = 0; nt < 4; nt++) {
                int r = mrow0 + mt * 16 + gid;
                int c = ncol0f + nt * 8 + tig * 2;
                float bb0 = b2[c], bb1 = b2[c + 1];
                int row = row0 + r;
                float v0 = fmaxf(acc2[mt][nt][0] + bb0, 0.f);
                float v1 = fmaxf(acc2[mt][nt][1] + bb1, 0.f);
                float v2 = fmaxf(acc2[mt][nt][2] + bb0, 0.f);
                float v3 = fmaxf(acc2[mt][nt][3] + bb1, 0.f);
                if (row < Nn) {
                    *(float2*)&hout[(size_t)row * 64 + c] = make_float2(v0, v1);
                } else { v0 = 0.f; v1 = 0.f; }
                if (row + 8 < Nn) {
                    *(float2*)&hout[(size_t)(row + 8) * 64 + c] = make_float2(v2, v3);
                } else { v2 = 0.f; v3 = 0.f; }
                Afw[r * FA_STRIDE + c] = v0;
                Afw[r * FA_STRIDE + c + 1] = v1;
                Afw[(r + 8) * FA_STRIDE + c] = v2;
                Afw[(r + 8) * FA_STRIDE + c + 1] = v3;
            }
        }
    }
    __syncthreads();

    if (tid < 128) {
        int f = tid & 63;
        bool sq = tid >= 64;
        const float* Afr = sm + L_ASH;
        float s = 0.f;
#pragma unroll 4
        for (int r = 0; r < 128; r++) {
            float v = Afr[r * FA_STRIDE + f];
            s += sq ? v * v : v;
        }
        g_part[blockIdx.x * 128 + tid] = s;
    }
}

// ---------------- BN finalize: grid=64 (one CTA per feature) ----------------
__global__ void __launch_bounds__(256)
k_bnfin(const float* __restrict__ gamma, const float* __restrict__ beta) {
    __shared__ float red[512];
    int f = blockIdx.x, tid = threadIdx.x;
    float s = 0.f, q = 0.f;
    for (int c = tid; c < NBMMA; c += 256) {
        s += g_part[c * 128 + f];
        q += g_part[c * 128 + 64 + f];
    }
    red[tid] = s;
    red[256 + tid] = q;
    __syncthreads();
    for (int off = 128; off > 0; off >>= 1) {
        if (tid < off) {
            red[tid] += red[tid + off];
            red[256 + tid] += red[256 + tid + off];
        }
        __syncthreads();
    }
    if (tid == 0) {
        float mean = red[0] * (1.0f / Nn);
        float var = red[256] * (1.0f / Nn) - mean * mean;
        float sc = gamma[f] * rsqrtf(var + BN_EPS);
        g_scale[f] = sc;
        g_shift[f] = fmaf(-mean, sc, beta[f]);
    }
}

// ---------------- pooling + head ----------------
__global__ void k_bounds(const int* __restrict__ batch) {
    int g = blockIdx.x * blockDim.x + threadIdx.x;
    if (g > Gg) return;
    if (g == Gg) { g_bstart[Gg] = Nn; return; }
    int lo = 0, hi = Nn;
    while (lo < hi) {
        int mid = (lo + hi) >> 1;
        if (batch[mid] < g) lo = mid + 1; else hi = mid;
    }
    g_bstart[g] = lo;
}
__global__ void k_pool(const float* __restrict__ h) {
    int g = blockIdx.x, d = threadIdx.x;
    int r0 = g_bstart[g], r1 = g_bstart[g + 1];
    float sc = g_scale[d], sh = g_shift[d];
    float s = 0.f;
    for (int r = r0; r < r1; r++) s += fmaf(h[r * 64 + d], sc, sh);
    g_gpool[g * 64 + d] = s;
}
__global__ void k_head(const float* __restrict__ fc1b, const float* __restrict__ fc2b,
                       float* __restrict__ out) {
    __shared__ float gsm[64], tsm[64];
    int g = blockIdx.x, d = threadIdx.x;
    gsm[d] = g_gpool[g * 64 + d];
    __syncthreads();
    float acc = fc1b[d];
    for (int k = 0; k < 64; k++) acc = fmaf(gsm[k], g_fc1Wt[k * 64 + d], acc);
    tsm[d] = fmaxf(acc, 0.f);
    __syncthreads();
    if (d < OUTD) {
        float a2 = fc2b[d];
        for (int k = 0; k < 64; k++) a2 = fmaf(tsm[k], g_fc2Wt[k * 16 + d], a2);
        out[g * OUTD + d] = a2;
    }
}

// ---------------- host ----------------
extern "C" void kernel_launch(void* const* d_in, const int* in_sizes, int n_in,
                              void* d_out, int out_size) {
    const float* x    = (const float*)d_in[0];
    const int*   ei   = (const int*)d_in[1];
    const int*   src  = ei;
    const int*   dst  = ei + Ee;
    const int*   batch = (const int*)d_in[2];
    const float* encW = (const float*)d_in[3];
    const float* encb = (const float*)d_in[4];
    const float* nnW1 = (const float*)d_in[5];
    const float* nnb1 = (const float*)d_in[6];
    const float* nnW2 = (const float*)d_in[7];
    const float* nnb2 = (const float*)d_in[8];
    const float* mlpW = (const float*)d_in[9];
    const float* mlpb = (const float*)d_in[10];
    const float* bnG  = (const float*)d_in[11];
    const float* bnB  = (const float*)d_in[12];
    const float* fc1W = (const float*)d_in[13];
    const float* fc1b = (const float*)d_in[14];
    const float* fc2W = (const float*)d_in[15];
    const float* fc2b = (const float*)d_in[16];
    float* out = (float*)d_out;

    float *p_h0, *p_h1, *p_encWt, *p_fc1Wt, *p_mlpBh, *p_mlpBl;
    float *p_W1h, *p_W1l, *p_W2h, *p_W2l;
    cudaGetSymbolAddress((void**)&p_h0, g_h0);
    cudaGetSymbolAddress((void**)&p_h1, g_h1);
    cudaGetSymbolAddress((void**)&p_encWt, g_encWt);
    cudaGetSymbolAddress((void**)&p_fc1Wt, g_fc1Wt);
    cudaGetSymbolAddress((void**)&p_mlpBh, g_mlpBh);
    cudaGetSymbolAddress((void**)&p_mlpBl, g_mlpBl);
    cudaGetSymbolAddress((void**)&p_W1h, g_nnW1h);
    cudaGetSymbolAddress((void**)&p_W1l, g_nnW1l);
    cudaGetSymbolAddress((void**)&p_W2h, g_nnW2h);
    cudaGetSymbolAddress((void**)&p_W2l, g_nnW2l);

    cudaFuncSetAttribute(k_layer, cudaFuncAttributeMaxDynamicSharedMemorySize, L_SMEM_BYTES);

    const int NB_SCAN = (Nn + 1023) / 1024;

    // CSR build
    k_zero_deg<<<(Nn + 255) / 256, 256>>>();
    k_count<<<(Ee + 255) / 256, 256>>>(dst);
    k_scan_block<<<NB_SCAN, 1024>>>();
    k_scan_tops<<<1, 128>>>(NB_SCAN);
    k_rowptr<<<(Nn + 255) / 256, 256>>>();
    k_scatter<<<(Ee + 255) / 256, 256>>>(src, dst);
    k_sortrows<<<(Nn + 255) / 256, 256>>>();

    // weight prep (k_tfc2 also sets identity affine for layer 0)
    k_t64<<<(4096 + 255) / 256, 256>>>(encW, p_encWt, 1);
    k_t64<<<(4096 + 255) / 256, 256>>>(fc1W, p_fc1Wt, 1);
    k_t64split<<<(5 * 4096 + 255) / 256, 256>>>(nnW1, p_W1h, p_W1l, 5);
    k_t64split<<<(5 * 4096 + 255) / 256, 256>>>(nnW2, p_W2h, p_W2l, 5);
    k_tmlpB<<<(NL * 256 * 192 + 255) / 256, 256>>>(mlpW);
    k_tfc2<<<(Dd * OUTD + 255) / 256, 256>>>(fc2W);

    const int NBLIN = NnP / 64;

    k_lin64<false><<<NBLIN, 64>>>(x, p_encWt, encb, p_h0);

    float* hbuf[2] = {p_h0, p_h1};
    for (int i = 0; i < NL; i++) {
        k_layer<<<NBMMA, 384, L_SMEM_BYTES>>>(hbuf[i & 1], hbuf[(i + 1) & 1],
                                              p_mlpBh + i * 49152, p_mlpBl + i * 49152,
                                              mlpb + i * Dd,
                                              p_W1h + i * 4096, p_W1l + i * 4096,
                                              p_W2h + i * 4096, p_W2l + i * 4096,
                                              nnb1 + i * Dd, nnb2 + i * Dd);
        k_bnfin<<<64, 256>>>(bnG + i * Dd, bnB + i * Dd);
    }

    k_bounds<<<(Gg + 1 + 255) / 256, 256>>>(batch);
    k_pool<<<Gg, 64>>>(hbuf[NL & 1]);
    k_head<<<Gg, 64>>>(fc1b, fc2b, out);
}

// round 13
// speedup vs baseline: 1.1340x; 1.1340x over previous
#include <cuda_runtime.h>
#include <cfloat>
#include <cstdint>

#define Nn 100000
#define NnP 100096          // multiple of 128 (MMA tile)
#define Ee 1600000
#define Dd 64
#define Gg 512
#define OUTD 16
#define NL 5
#define DELTA 2.5749f
#define BN_EPS 1e-5f
#define NBMMA (NnP / 128)   // 782

// ---------------- static device scratch ----------------
static __device__ float g_hB[NnP * Dd];        // node features (pre-BN)
static __device__ float g_baseF[NnP * 256];    // [sum|max|mean|var] fp32
static __device__ float g_cfac[NnP];
static __device__ int   g_deg[Nn];
static __device__ int   g_sc[Nn];
static __device__ int   g_bsum[128];
static __device__ int   g_rowptr[Nn + 1];
static __device__ int   g_cursor[Nn];
static __device__ int   g_esrc[Ee];
static __device__ float g_part[NBMMA * 128];   // per-CTA BN partials
static __device__ float g_scale[Dd];
static __device__ float g_shift[Dd];
static __device__ int   g_bstart[Gg + 1];
static __device__ float g_gpool[Gg * Dd];
static __device__ float g_encWt[Dd * Dd];
static __device__ float g_nnW1h[NL * Dd * Dd];  // [k][d] tf32 hi
static __device__ float g_nnW1l[NL * Dd * Dd];
static __device__ float g_nnW2h[NL * Dd * Dd];
static __device__ float g_nnW2l[NL * Dd * Dd];
static __device__ float g_mlpBh[NL * 256 * 192];  // [k][n], tf32 hi
static __device__ float g_mlpBl[NL * 256 * 192];
static __device__ float g_fc1Wt[Dd * Dd];
static __device__ float g_fc2Wt[Dd * OUTD];

__device__ __forceinline__ float tf32r(float x) {
    float y;
    asm("cvt.rna.tf32.f32 %0, %1;" : "=f"(y) : "f"(x));
    return y;
}
__device__ __forceinline__ void mma1688(float* c, const uint32_t* a, uint32_t b0, uint32_t b1) {
    asm volatile(
        "mma.sync.aligned.m16n8k8.row.col.f32.tf32.tf32.f32 "
        "{%0,%1,%2,%3}, {%4,%5,%6,%7}, {%8,%9}, {%0,%1,%2,%3};"
        : "+f"(c[0]), "+f"(c[1]), "+f"(c[2]), "+f"(c[3])
        : "r"(a[0]), "r"(a[1]), "r"(a[2]), "r"(a[3]), "r"(b0), "r"(b1));
}
__device__ __forceinline__ uint32_t smem_u32(const void* p) {
    uint32_t a;
    asm("{ .reg .u64 t; cvta.to.shared.u64 t, %1; cvt.u32.u64 %0, t; }" : "=r"(a) : "l"(p));
    return a;
}
__device__ __forceinline__ void cp16(uint32_t d, const void* s) {
    asm volatile("cp.async.cg.shared.global [%0], [%1], 16;" :: "r"(d), "l"(s));
}
#define CP_COMMIT() asm volatile("cp.async.commit_group;" ::: "memory")
#define CP_WAIT(n)  asm volatile("cp.async.wait_group %0;" :: "n"(n) : "memory")

// ---------------- CSR build ----------------
__global__ void k_zero_deg() {
    int i = blockIdx.x * blockDim.x + threadIdx.x;
    if (i < Nn) g_deg[i] = 0;
}
__global__ void k_count(const int* __restrict__ dst) {
    int e = blockIdx.x * blockDim.x + threadIdx.x;
    if (e < Ee) atomicAdd(&g_deg[dst[e]], 1);
}
__global__ void k_scan_block() {
    __shared__ int sm[1024];
    int i = blockIdx.x * 1024 + threadIdx.x;
    int v = (i < Nn) ? g_deg[i] : 0;
    sm[threadIdx.x] = v;
    __syncthreads();
    for (int off = 1; off < 1024; off <<= 1) {
        int t = 0;
        if (threadIdx.x >= off) t = sm[threadIdx.x - off];
        __syncthreads();
        sm[threadIdx.x] += t;
        __syncthreads();
    }
    if (i < Nn) g_sc[i] = sm[threadIdx.x];
    if (threadIdx.x == 1023) g_bsum[blockIdx.x] = sm[1023];
}
// parallel exclusive scan over block sums (nb <= 128)
__global__ void k_scan_tops(int nb) {
    __shared__ int sm2[128];
    int t = threadIdx.x;
    int v = (t < nb) ? g_bsum[t] : 0;
    sm2[t] = v;
    __syncthreads();
    for (int off = 1; off < 128; off <<= 1) {
        int u = (t >= off) ? sm2[t - off] : 0;
        __syncthreads();
        sm2[t] += u;
        __syncthreads();
    }
    if (t < nb) g_bsum[t] = sm2[t] - v;
}
__global__ void k_rowptr() {
    int i = blockIdx.x * blockDim.x + threadIdx.x;
    if (i < Nn) {
        int rp = g_sc[i] - g_deg[i] + g_bsum[i >> 10];
        g_rowptr[i] = rp;
        g_cursor[i] = rp;
        g_cfac[i] = fmaxf((float)g_deg[i], 1.0f);
    }
    if (i == 0) g_rowptr[Nn] = Ee;
}
__global__ void k_scatter(const int* __restrict__ src, const int* __restrict__ dst) {
    int e = blockIdx.x * blockDim.x + threadIdx.x;
    if (e < Ee) {
        int p = atomicAdd(&g_cursor[dst[e]], 1);
        g_esrc[p] = src[e];
    }
}
__global__ void k_sortrows() {
    int n = blockIdx.x * blockDim.x + threadIdx.x;
    if (n >= Nn) return;
    int beg = g_rowptr[n], end = g_rowptr[n + 1];
    int deg = end - beg;
    if (deg <= 1) return;
    if (deg <= 64) {
        int buf[64];
        for (int i = 0; i < deg; i++) buf[i] = g_esrc[beg + i];
        for (int i = 1; i < deg; i++) {
            int v = buf[i];
            int j = i - 1;
            while (j >= 0 && buf[j] > v) { buf[j + 1] = buf[j]; j--; }
            buf[j + 1] = v;
        }
        for (int i = 0; i < deg; i++) g_esrc[beg + i] = buf[i];
    } else {
        for (int i = beg + 1; i < end; i++) {
            int v = g_esrc[i];
            int j = i - 1;
            while (j >= beg && g_esrc[j] > v) { g_esrc[j + 1] = g_esrc[j]; j--; }
            g_esrc[j + 1] = v;
        }
    }
}

// ---------------- weight prep ----------------
__global__ void k_t64(const float* __restrict__ W, float* __restrict__ Wt, int nm) {
    int idx = blockIdx.x * blockDim.x + threadIdx.x;
    if (idx >= nm * 4096) return;
    int m = idx >> 12, r = idx & 4095;
    int d = r >> 6, k = r & 63;
    Wt[(m << 12) + (k << 6) + d] = W[idx];
}
__global__ void k_t64split(const float* __restrict__ W, float* __restrict__ Wh,
                           float* __restrict__ Wl, int nm) {
    int idx = blockIdx.x * blockDim.x + threadIdx.x;
    if (idx >= nm * 4096) return;
    int m = idx >> 12, r = idx & 4095;
    int d = r >> 6, k = r & 63;
    float w = W[idx];
    float h = tf32r(w);
    Wh[(m << 12) + (k << 6) + d] = h;
    Wl[(m << 12) + (k << 6) + d] = tf32r(w - h);
}
__global__ void k_tmlpB(const float* __restrict__ W) {
    int idx = blockIdx.x * blockDim.x + threadIdx.x;
    if (idx >= NL * 256 * 192) return;
    int m = idx / 49152, r = idx % 49152;
    int k = r / 192, n = r % 192;
    int d = n & 63, b = n >> 6;
    float w = W[m * 49152 + d * 768 + b * 256 + k];
    float h = tf32r(w);
    g_mlpBh[idx] = h;
    g_mlpBl[idx] = tf32r(w - h);
}
// also initializes identity affine for layer 0
__global__ void k_tfc2(const float* __restrict__ W) {
    int idx = blockIdx.x * blockDim.x + threadIdx.x;
    if (idx < 64) { g_scale[idx] = 1.0f; g_shift[idx] = 0.0f; }
    if (idx >= Dd * OUTD) return;
    int o = idx >> 6, k = idx & 63;
    g_fc2Wt[k * 16 + o] = W[idx];
}

// ---------------- 64x64 linear (encoder only) ----------------
template <bool RELU>
__global__ void __launch_bounds__(64) k_lin64(const float* __restrict__ A,
                                              const float* __restrict__ Wt,
                                              const float* __restrict__ b,
                                              float* __restrict__ C) {
    __shared__ float4 Asm[64][16];
    int row0 = blockIdx.x * 64, tid = threadIdx.x;
    for (int t = tid; t < 1024; t += 64) {
        int r = t >> 4, c = t & 15;
        float4 v = make_float4(0.f, 0.f, 0.f, 0.f);
        if (row0 + r < Nn) v = ((const float4*)A)[(row0 + r) * 16 + c];
        Asm[r][c] = v;
    }
    __syncthreads();
    float acc[64];
#pragma unroll
    for (int r = 0; r < 64; r++) acc[r] = 0.f;
#pragma unroll 1
    for (int k4 = 0; k4 < 16; k4++) {
        float w0 = Wt[(k4 * 4 + 0) * 64 + tid];
        float w1 = Wt[(k4 * 4 + 1) * 64 + tid];
        float w2 = Wt[(k4 * 4 + 2) * 64 + tid];
        float w3 = Wt[(k4 * 4 + 3) * 64 + tid];
#pragma unroll
        for (int r = 0; r < 64; r++) {
            float4 a = Asm[r][k4];
            float t0 = fmaf(a.x, w0, acc[r]);
            t0 = fmaf(a.y, w1, t0);
            t0 = fmaf(a.z, w2, t0);
            acc[r] = fmaf(a.w, w3, t0);
        }
    }
    float bb = b[tid];
    for (int r = 0; r < 64; r++) {
        if (row0 + r < Nn) {
            float v = acc[r] + bb;
            if (RELU) v = fmaxf(v, 0.f);
            C[(row0 + r) * 64 + tid] = v;
        }
    }
}

// ---------------- PNA aggregation (warp/node, affine on the fly, 4-way unroll) ----------------
__global__ void k_agg() {
    int gt = blockIdx.x * blockDim.x + threadIdx.x;
    int w = gt >> 5, lane = gt & 31;
    if (w >= Nn) return;
    int beg = g_rowptr[w], end = g_rowptr[w + 1];
    const float2* hp = (const float2*)g_hB;
    float scx = g_scale[2 * lane], scy = g_scale[2 * lane + 1];
    float shx = g_shift[2 * lane], shy = g_shift[2 * lane + 1];
    float sxA = 0.f, syA = 0.f, qxA = 0.f, qyA = 0.f;
    float sxB = 0.f, syB = 0.f, qxB = 0.f, qyB = 0.f;
    float mxx = -FLT_MAX, mxy = -FLT_MAX;
    int j = beg;
    for (; j + 3 < end; j += 4) {
        int s0 = g_esrc[j];
        int s1 = g_esrc[j + 1];
        int s2 = g_esrc[j + 2];
        int s3 = g_esrc[j + 3];
        float2 r0 = hp[s0 * 32 + lane];
        float2 r1 = hp[s1 * 32 + lane];
        float2 r2 = hp[s2 * 32 + lane];
        float2 r3 = hp[s3 * 32 + lane];
        float v0x = fmaf(r0.x, scx, shx), v0y = fmaf(r0.y, scy, shy);
        float v1x = fmaf(r1.x, scx, shx), v1y = fmaf(r1.y, scy, shy);
        float v2x = fmaf(r2.x, scx, shx), v2y = fmaf(r2.y, scy, shy);
        float v3x = fmaf(r3.x, scx, shx), v3y = fmaf(r3.y, scy, shy);
        sxA += v0x; syA += v0y;
        qxA = fmaf(v0x, v0x, qxA); qyA = fmaf(v0y, v0y, qyA);
        mxx = fmaxf(mxx, v0x); mxy = fmaxf(mxy, v0y);
        sxB += v1x; syB += v1y;
        qxB = fmaf(v1x, v1x, qxB); qyB = fmaf(v1y, v1y, qyB);
        mxx = fmaxf(mxx, v1x); mxy = fmaxf(mxy, v1y);
        sxA += v2x; syA += v2y;
        qxA = fmaf(v2x, v2x, qxA); qyA = fmaf(v2y, v2y, qyA);
        mxx = fmaxf(mxx, v2x); mxy = fmaxf(mxy, v2y);
        sxB += v3x; syB += v3y;
        qxB = fmaf(v3x, v3x, qxB); qyB = fmaf(v3y, v3y, qyB);
        mxx = fmaxf(mxx, v3x); mxy = fmaxf(mxy, v3y);
    }
    for (; j < end; j++) {
        int s0 = g_esrc[j];
        float2 r0 = hp[s0 * 32 + lane];
        float v0x = fmaf(r0.x, scx, shx), v0y = fmaf(r0.y, scy, shy);
        sxA += v0x; syA += v0y;
        qxA = fmaf(v0x, v0x, qxA); qyA = fmaf(v0y, v0y, qyA);
        mxx = fmaxf(mxx, v0x); mxy = fmaxf(mxy, v0y);
    }
    float sx = sxA + sxB, sy = syA + syB;
    float qx = qxA + qxB, qy = qyA + qyB;
    if (end == beg) { mxx = 0.f; mxy = 0.f; }
    float c = g_cfac[w];
    float inv = 1.f / c;
    float mex = sx * inv, mey = sy * inv;
    float vx = fmaxf(qx * inv - mex * mex, 0.f);
    float vy = fmaxf(qy * inv - mey * mey, 0.f);
    float2* bp = (float2*)(g_baseF + (size_t)w * 256);
    bp[lane]      = make_float2(sx, sy);
    bp[32 + lane] = make_float2(mxx, mxy);
    bp[64 + lane] = make_float2(mex, mey);
    bp[96 + lane] = make_float2(vx, vy);
}

// ---------------- merged layer kernel (fp32 A, in-register hi/lo split) ----------------
// phase 1: pipelined 3xTF32 GEMM S = base @ B  (12 warps, 4m x 3n)
// phase 2: stage S + prefetch W1; combine -> nn A fragments (smem)
// phase 3: nn stage1/stage2 (warps 0-7, 4m x 2n), W2 prefetched under resplit
// phase 4: epilogue writes g_hB + deterministic BN partials
#define AS_STRIDE 36
#define BS_STRIDE 200
#define SS_STRIDE 200
#define P_A  0
#define P_BH 4608
#define P_BL 11008
#define PSTG 17408
#define FA_STRIDE 68
#define FW_STRIDE 72
#define L_ASH 25600
#define L_ASL (L_ASH + 128 * FA_STRIDE)   // 34304
#define L_WH  (L_ASL + 128 * FA_STRIDE)   // 43008
#define L_WL  (L_WH + 64 * FW_STRIDE)     // 47616
#define L_SMEM_FLOATS (L_WL + 64 * FW_STRIDE)  // 52224
#define L_SMEM_BYTES (L_SMEM_FLOATS * 4)       // 208896

__global__ void __launch_bounds__(384)
k_layer(const float* __restrict__ Bh, const float* __restrict__ Bl,
        const float* __restrict__ mb,
        const float* __restrict__ W1h, const float* __restrict__ W1l,
        const float* __restrict__ W2h, const float* __restrict__ W2l,
        const float* __restrict__ b1, const float* __restrict__ b2) {
    extern __shared__ float sm[];
    uint32_t sb = smem_u32(sm);
    int tid = threadIdx.x, wid = tid >> 5, lane = tid & 31;
    int gid = lane >> 2, tig = lane & 3;
    int row0 = blockIdx.x * 128;
    int mrow0 = (wid & 3) * 32;
    int ncol0p = (wid >> 2) * 64;   // pna n offset
    int ncol0f = (wid >> 2) * 32;   // nn n offset (warps 0-7)

    // async load of one kc stage (A fp32 + B hi/lo) into buffer `buf`
    auto load_stage = [&](int kc, int buf) {
        uint32_t aA = sb + (uint32_t)(buf * PSTG + P_A) * 4;
        uint32_t bH = sb + (uint32_t)(buf * PSTG + P_BH) * 4;
        uint32_t bL = sb + (uint32_t)(buf * PSTG + P_BL) * 4;
        for (int i = tid; i < 1024; i += 384) {
            int r = i >> 3, c4 = i & 7;
            uint32_t off = (uint32_t)(r * AS_STRIDE + c4 * 4) * 4;
            cp16(aA + off, &g_baseF[(size_t)(row0 + r) * 256 + kc * 32 + c4 * 4]);
        }
        for (int i = tid; i < 1536; i += 384) {
            int r = i / 48, c4 = i % 48;
            uint32_t off = (uint32_t)(r * BS_STRIDE + c4 * 4) * 4;
            size_t go = (size_t)(kc * 32 + r) * 192 + c4 * 4;
            cp16(bH + off, &Bh[go]);
            cp16(bL + off, &Bl[go]);
        }
    };

    float acc[2][8][4];
#pragma unroll
    for (int mt = 0; mt < 2; mt++)
#pragma unroll
        for (int nt = 0; nt < 8; nt++)
#pragma unroll
            for (int j = 0; j < 4; j++) acc[mt][nt][j] = 0.f;

    load_stage(0, 0);
    CP_COMMIT();

#pragma unroll 1
    for (int kc = 0; kc < 8; kc++) {
        if (kc < 7) {
            load_stage(kc + 1, (kc + 1) & 1);
            CP_COMMIT();
            CP_WAIT(1);
        } else {
            CP_WAIT(0);
        }
        __syncthreads();
        const float* As  = sm + (kc & 1) * PSTG + P_A;
        const float* Bsh = sm + (kc & 1) * PSTG + P_BH;
        const float* Bsl = sm + (kc & 1) * PSTG + P_BL;
#pragma unroll
        for (int k8 = 0; k8 < 4; k8++) {
            int kb = k8 * 8;
            uint32_t ah[2][4], al[2][4];
#pragma unroll
            for (int mt = 0; mt < 2; mt++) {
                int mr = mrow0 + mt * 16 + gid;
                float a0 = As[mr * AS_STRIDE + kb + tig];
                float a1 = As[(mr + 8) * AS_STRIDE + kb + tig];
                float a2 = As[mr * AS_STRIDE + kb + tig + 4];
                float a3 = As[(mr + 8) * AS_STRIDE + kb + tig + 4];
                float h0 = tf32r(a0), h1 = tf32r(a1), h2 = tf32r(a2), h3 = tf32r(a3);
                ah[mt][0] = __float_as_uint(h0);
                ah[mt][1] = __float_as_uint(h1);
                ah[mt][2] = __float_as_uint(h2);
                ah[mt][3] = __float_as_uint(h3);
                al[mt][0] = __float_as_uint(tf32r(a0 - h0));
                al[mt][1] = __float_as_uint(tf32r(a1 - h1));
                al[mt][2] = __float_as_uint(tf32r(a2 - h2));
                al[mt][3] = __float_as_uint(tf32r(a3 - h3));
            }
#pragma unroll
            for (int nt = 0; nt < 8; nt++) {
                int nc = ncol0p + nt * 8 + gid;
                uint32_t bh0 = __float_as_uint(Bsh[(kb + tig) * BS_STRIDE + nc]);
                uint32_t bh1 = __float_as_uint(Bsh[(kb + tig + 4) * BS_STRIDE + nc]);
                uint32_t bl0 = __float_as_uint(Bsl[(kb + tig) * BS_STRIDE + nc]);
                uint32_t bl1 = __float_as_uint(Bsl[(kb + tig + 4) * BS_STRIDE + nc]);
                mma1688(acc[0][nt], ah[0], bh0, bh1);
                mma1688(acc[0][nt], ah[0], bl0, bl1);
                mma1688(acc[0][nt], al[0], bh0, bh1);
                mma1688(acc[1][nt], ah[1], bh0, bh1);
                mma1688(acc[1][nt], ah[1], bl0, bl1);
                mma1688(acc[1][nt], al[1], bh0, bh1);
            }
        }
        __syncthreads();
    }

    // ---- phase 2: prefetch W1, stage S, combine -> nn fragments ----
    {
        uint32_t whA = sb + L_WH * 4, wlA = sb + L_WL * 4;
        for (int i = tid; i < 2048; i += 384) {
            int c = i & 1023;
            int k = c >> 4, c4 = c & 15;
            uint32_t off = (uint32_t)(k * FW_STRIDE + c4 * 4) * 4;
            if (i < 1024) cp16(whA + off, &W1h[c * 4]);
            else          cp16(wlA + off, &W1l[c * 4]);
        }
        CP_COMMIT();
    }
#pragma unroll
    for (int mt = 0; mt < 2; mt++) {
#pragma unroll
        for (int nt = 0; nt < 8; nt++) {
            int r = mrow0 + mt * 16 + gid;
            int c = ncol0p + nt * 8 + tig * 2;
            *(float2*)&sm[r * SS_STRIDE + c] = make_float2(acc[mt][nt][0], acc[mt][nt][1]);
            *(float2*)&sm[(r + 8) * SS_STRIDE + c] = make_float2(acc[mt][nt][2], acc[mt][nt][3]);
        }
    }
    __syncthreads();

    // combine: u = affine(hB) + mb + S0 + (c/D)S1 + (D/c)S2 -> split into frags
    {
        float* Af = sm + L_ASH;
        float* Al = sm + L_ASL;
        for (int i = tid; i < 128 * 64; i += 384) {
            int r = i >> 6, d = i & 63;
            int row = row0 + r;
            float h = 0.f, l = 0.f;
            if (row < Nn) {
                float cf = g_cfac[row];
                float aa = cf * (1.0f / DELTA);
                float b2c = DELTA / cf;
                const float* Sr = sm + r * SS_STRIDE;
                float x = fmaf(g_hB[(size_t)row * 64 + d], g_scale[d], g_shift[d]);
                float v = x + mb[d] + Sr[d] + aa * Sr[64 + d] + b2c * Sr[128 + d];
                h = tf32r(v);
                l = tf32r(v - h);
            }
            Af[r * FA_STRIDE + d] = h;
            Al[r * FA_STRIDE + d] = l;
        }
    }
    CP_WAIT(0);
    __syncthreads();

    // ---- phase 3: nn stage 1 (warps 0-7) ----
    float acc2[2][4][4];
    const float* Af = sm + L_ASH;
    const float* Al = sm + L_ASL;
    const float* wh = sm + L_WH;
    const float* wl = sm + L_WL;
    if (wid < 8) {
#pragma unroll
        for (int mt = 0; mt < 2; mt++)
#pragma unroll
            for (int nt = 0; nt < 4; nt++)
#pragma unroll
                for (int j = 0; j < 4; j++) acc2[mt][nt][j] = 0.f;
#pragma unroll 1
        for (int k8 = 0; k8 < 8; k8++) {
            int kb = k8 * 8;
            uint32_t ah[2][4], al2[2][4];
#pragma unroll
            for (int mt = 0; mt < 2; mt++) {
                int mr = mrow0 + mt * 16 + gid;
                ah[mt][0] = __float_as_uint(Af[mr * FA_STRIDE + kb + tig]);
                ah[mt][1] = __float_as_uint(Af[(mr + 8) * FA_STRIDE + kb + tig]);
                ah[mt][2] = __float_as_uint(Af[mr * FA_STRIDE + kb + tig + 4]);
                ah[mt][3] = __float_as_uint(Af[(mr + 8) * FA_STRIDE + kb + tig + 4]);
                al2[mt][0] = __float_as_uint(Al[mr * FA_STRIDE + kb + tig]);
                al2[mt][1] = __float_as_uint(Al[(mr + 8) * FA_STRIDE + kb + tig]);
                al2[mt][2] = __float_as_uint(Al[mr * FA_STRIDE + kb + tig + 4]);
                al2[mt][3] = __float_as_uint(Al[(mr + 8) * FA_STRIDE + kb + tig + 4]);
            }
#pragma unroll
            for (int nt = 0; nt < 4; nt++) {
                int nc = ncol0f + nt * 8 + gid;
                uint32_t bh0 = __float_as_uint(wh[(kb + tig) * FW_STRIDE + nc]);
                uint32_t bh1 = __float_as_uint(wh[(kb + tig + 4) * FW_STRIDE + nc]);
                uint32_t bl0 = __float_as_uint(wl[(kb + tig) * FW_STRIDE + nc]);
                uint32_t bl1 = __float_as_uint(wl[(kb + tig + 4) * FW_STRIDE + nc]);
                mma1688(acc2[0][nt], ah[0], bh0, bh1);
                mma1688(acc2[0][nt], ah[0], bl0, bl1);
                mma1688(acc2[0][nt], al2[0], bh0, bh1);
                mma1688(acc2[1][nt], ah[1], bh0, bh1);
                mma1688(acc2[1][nt], ah[1], bl0, bl1);
                mma1688(acc2[1][nt], al2[1], bh0, bh1);
            }
        }
    }
    __syncthreads();   // all reads of W1 + A fragments done

    // async load W2 into same weight buffer; hide under relu-resplit
    {
        uint32_t whA = sb + L_WH * 4, wlA = sb + L_WL * 4;
        for (int i = tid; i < 2048; i += 384) {
            int c = i & 1023;
            int k = c >> 4, c4 = c & 15;
            uint32_t off = (uint32_t)(k * FW_STRIDE + c4 * 4) * 4;
            if (i < 1024) cp16(whA + off, &W2h[c * 4]);
            else          cp16(wlA + off, &W2l[c * 4]);
        }
        CP_COMMIT();
    }
    // relu + bias, re-split into A fragments
    if (wid < 8) {
        float* Afw = sm + L_ASH;
        float* Alw = sm + L_ASL;
#pragma unroll
        for (int mt = 0; mt < 2; mt++) {
#pragma unroll
            for (int nt = 0; nt < 4; nt++) {
                int r = mrow0 + mt * 16 + gid;
                int c = ncol0f + nt * 8 + tig * 2;
                float bb0 = b1[c], bb1 = b1[c + 1];
                float u0 = fmaxf(acc2[mt][nt][0] + bb0, 0.f);
                float u1 = fmaxf(acc2[mt][nt][1] + bb1, 0.f);
                float u2 = fmaxf(acc2[mt][nt][2] + bb0, 0.f);
                float u3 = fmaxf(acc2[mt][nt][3] + bb1, 0.f);
                float h0 = tf32r(u0), h1 = tf32r(u1), h2 = tf32r(u2), h3 = tf32r(u3);
                Afw[r * FA_STRIDE + c] = h0;
                Afw[r * FA_STRIDE + c + 1] = h1;
                Afw[(r + 8) * FA_STRIDE + c] = h2;
                Afw[(r + 8) * FA_STRIDE + c + 1] = h3;
                Alw[r * FA_STRIDE + c] = tf32r(u0 - h0);
                Alw[r * FA_STRIDE + c + 1] = tf32r(u1 - h1);
                Alw[(r + 8) * FA_STRIDE + c] = tf32r(u2 - h2);
                Alw[(r + 8) * FA_STRIDE + c + 1] = tf32r(u3 - h3);
            }
        }
    }
    CP_WAIT(0);
    __syncthreads();

    // ---- nn stage 2 ----
    if (wid < 8) {
#pragma unroll
        for (int mt = 0; mt < 2; mt++)
#pragma unroll
            for (int nt = 0; nt < 4; nt++)
#pragma unroll
                for (int j = 0; j < 4; j++) acc2[mt][nt][j] = 0.f;
#pragma unroll 1
        for (int k8 = 0; k8 < 8; k8++) {
            int kb = k8 * 8;
            uint32_t ah[2][4], al2[2][4];
#pragma unroll
            for (int mt = 0; mt < 2; mt++) {
                int mr = mrow0 + mt * 16 + gid;
                ah[mt][0] = __float_as_uint(Af[mr * FA_STRIDE + kb + tig]);
                ah[mt][1] = __float_as_uint(Af[(mr + 8) * FA_STRIDE + kb + tig]);
                ah[mt][2] = __float_as_uint(Af[mr * FA_STRIDE + kb + tig + 4]);
                ah[mt][3] = __float_as_uint(Af[(mr + 8) * FA_STRIDE + kb + tig + 4]);
                al2[mt][0] = __float_as_uint(Al[mr * FA_STRIDE + kb + tig]);
                al2[mt][1] = __float_as_uint(Al[(mr + 8) * FA_STRIDE + kb + tig]);
                al2[mt][2] = __float_as_uint(Al[mr * FA_STRIDE + kb + tig + 4]);
                al2[mt][3] = __float_as_uint(Al[(mr + 8) * FA_STRIDE + kb + tig + 4]);
            }
#pragma unroll
            for (int nt = 0; nt < 4; nt++) {
                int nc = ncol0f + nt * 8 + gid;
                uint32_t bh0 = __float_as_uint(wh[(kb + tig) * FW_STRIDE + nc]);
                uint32_t bh1 = __float_as_uint(wh[(kb + tig + 4) * FW_STRIDE + nc]);
                uint32_t bl0 = __float_as_uint(wl[(kb + tig) * FW_STRIDE + nc]);
                uint32_t bl1 = __float_as_uint(wl[(kb + tig + 4) * FW_STRIDE + nc]);
                mma1688(acc2[0][nt], ah[0], bh0, bh1);
                mma1688(acc2[0][nt], ah[0], bl0, bl1);
                mma1688(acc2[0][nt], al2[0], bh0, bh1);
                mma1688(acc2[1][nt], ah[1], bh0, bh1);
                mma1688(acc2[1][nt], ah[1], bl0, bl1);
                mma1688(acc2[1][nt], al2[1], bh0, bh1);
            }
        }
    }
    __syncthreads();   // A fragments free for output staging

    // ---- phase 4: epilogue (outer relu) + BN staging ----
    if (wid < 8) {
        float* Afw = sm + L_ASH;
#pragma unroll
        for (int mt = 0; mt < 2; mt++) {
#pragma unroll
            for (int nt = 0; nt < 4; nt++) {
                int r = mrow0 + mt * 16 + gid;
                int c = ncol0f + nt * 8 + tig * 2;
                float bb0 = b2[c], bb1 = b2[c + 1];
                int row = row0 + r;
                float v0 = fmaxf(acc2[mt][nt][0] + bb0, 0.f);
                float v1 = fmaxf(acc2[mt][nt][1] + bb1, 0.f);
                float v2 = fmaxf(acc2[mt][nt][2] + bb0, 0.f);
                float v3 = fmaxf(acc2[mt][nt][3] + bb1, 0.f);
                if (row < Nn) {
                    *(float2*)&g_hB[(size_t)row * 64 + c] = make_float2(v0, v1);
                } else { v0 = 0.f; v1 = 0.f; }
                if (row + 8 < Nn) {
                    *(float2*)&g_hB[(size_t)(row + 8) * 64 + c] = make_float2(v2, v3);
                } else { v2 = 0.f; v3 = 0.f; }
                Afw[r * FA_STRIDE + c] = v0;
                Afw[r * FA_STRIDE + c + 1] = v1;
                Afw[(r + 8) * FA_STRIDE + c] = v2;
                Afw[(r + 8) * FA_STRIDE + c + 1] = v3;
            }
        }
    }
    __syncthreads();

    if (tid < 128) {
        int f = tid & 63;
        bool sq = tid >= 64;
        const float* Afr = sm + L_ASH;
        float s = 0.f;
#pragma unroll 4
        for (int r = 0; r < 128; r++) {
            float v = Afr[r * FA_STRIDE + f];
            s += sq ? v * v : v;
        }
        g_part[blockIdx.x * 128 + tid] = s;
    }
}

// ---------------- BN finalize: grid=64 (one CTA per feature) ----------------
__global__ void __launch_bounds__(256)
k_bnfin(const float* __restrict__ gamma, const float* __restrict__ beta) {
    __shared__ float red[512];
    int f = blockIdx.x, tid = threadIdx.x;
    float s = 0.f, q = 0.f;
    for (int c = tid; c < NBMMA; c += 256) {
        s += g_part[c * 128 + f];
        q += g_part[c * 128 + 64 + f];
    }
    red[tid] = s;
    red[256 + tid] = q;
    __syncthreads();
    for (int off = 128; off > 0; off >>= 1) {
        if (tid < off) {
            red[tid] += red[tid + off];
            red[256 + tid] += red[256 + tid + off];
        }
        __syncthreads();
    }
    if (tid == 0) {
        float mean = red[0] * (1.0f / Nn);
        float var = red[256] * (1.0f / Nn) - mean * mean;
        float sc = gamma[f] * rsqrtf(var + BN_EPS);
        g_scale[f] = sc;
        g_shift[f] = fmaf(-mean, sc, beta[f]);
    }
}

// ---------------- pooling + head ----------------
__global__ void k_bounds(const int* __restrict__ batch) {
    int g = blockIdx.x * blockDim.x + threadIdx.x;
    if (g > Gg) return;
    if (g == Gg) { g_bstart[Gg] = Nn; return; }
    int lo = 0, hi = Nn;
    while (lo < hi) {
        int mid = (lo + hi) >> 1;
        if (batch[mid] < g) lo = mid + 1; else hi = mid;
    }
    g_bstart[g] = lo;
}
__global__ void k_pool() {
    int g = blockIdx.x, d = threadIdx.x;
    int r0 = g_bstart[g], r1 = g_bstart[g + 1];
    float sc = g_scale[d], sh = g_shift[d];
    float s = 0.f;
    for (int r = r0; r < r1; r++) s += fmaf(g_hB[r * 64 + d], sc, sh);
    g_gpool[g * 64 + d] = s;
}
__global__ void k_head(const float* __restrict__ fc1b, const float* __restrict__ fc2b,
                       float* __restrict__ out) {
    __shared__ float gsm[64], tsm[64];
    int g = blockIdx.x, d = threadIdx.x;
    gsm[d] = g_gpool[g * 64 + d];
    __syncthreads();
    float acc = fc1b[d];
    for (int k = 0; k < 64; k++) acc = fmaf(gsm[k], g_fc1Wt[k * 64 + d], acc);
    tsm[d] = fmaxf(acc, 0.f);
    __syncthreads();
    if (d < OUTD) {
        float a2 = fc2b[d];
        for (int k = 0; k < 64; k++) a2 = fmaf(tsm[k], g_fc2Wt[k * 16 + d], a2);
        out[g * OUTD + d] = a2;
    }
}

// ---------------- host ----------------
extern "C" void kernel_launch(void* const* d_in, const int* in_sizes, int n_in,
                              void* d_out, int out_size) {
    const float* x    = (const float*)d_in[0];
    const int*   ei   = (const int*)d_in[1];
    const int*   src  = ei;
    const int*   dst  = ei + Ee;
    const int*   batch = (const int*)d_in[2];
    const float* encW = (const float*)d_in[3];
    const float* encb = (const float*)d_in[4];
    const float* nnW1 = (const float*)d_in[5];
    const float* nnb1 = (const float*)d_in[6];
    const float* nnW2 = (const float*)d_in[7];
    const float* nnb2 = (const float*)d_in[8];
    const float* mlpW = (const float*)d_in[9];
    const float* mlpb = (const float*)d_in[10];
    const float* bnG  = (const float*)d_in[11];
    const float* bnB  = (const float*)d_in[12];
    const float* fc1W = (const float*)d_in[13];
    const float* fc1b = (const float*)d_in[14];
    const float* fc2W = (const float*)d_in[15];
    const float* fc2b = (const float*)d_in[16];
    float* out = (float*)d_out;

    float *p_hB, *p_encWt, *p_fc1Wt, *p_mlpBh, *p_mlpBl;
    float *p_W1h, *p_W1l, *p_W2h, *p_W2l;
    cudaGetSymbolAddress((void**)&p_hB, g_hB);
    cudaGetSymbolAddress((void**)&p_encWt, g_encWt);
    cudaGetSymbolAddress((void**)&p_fc1Wt, g_fc1Wt);
    cudaGetSymbolAddress((void**)&p_mlpBh, g_mlpBh);
    cudaGetSymbolAddress((void**)&p_mlpBl, g_mlpBl);
    cudaGetSymbolAddress((void**)&p_W1h, g_nnW1h);
    cudaGetSymbolAddress((void**)&p_W1l, g_nnW1l);
    cudaGetSymbolAddress((void**)&p_W2h, g_nnW2h);
    cudaGetSymbolAddress((void**)&p_W2l, g_nnW2l);

    cudaFuncSetAttribute(k_layer, cudaFuncAttributeMaxDynamicSharedMemorySize, L_SMEM_BYTES);

    const int NB_SCAN = (Nn + 1023) / 1024;

    // CSR build
    k_zero_deg<<<(Nn + 255) / 256, 256>>>();
    k_count<<<(Ee + 255) / 256, 256>>>(dst);
    k_scan_block<<<NB_SCAN, 1024>>>();
    k_scan_tops<<<1, 128>>>(NB_SCAN);
    k_rowptr<<<(Nn + 255) / 256, 256>>>();
    k_scatter<<<(Ee + 255) / 256, 256>>>(src, dst);
    k_sortrows<<<(Nn + 255) / 256, 256>>>();

    // weight prep (k_tfc2 also sets identity affine for layer 0)
    k_t64<<<(4096 + 255) / 256, 256>>>(encW, p_encWt, 1);
    k_t64<<<(4096 + 255) / 256, 256>>>(fc1W, p_fc1Wt, 1);
    k_t64split<<<(5 * 4096 + 255) / 256, 256>>>(nnW1, p_W1h, p_W1l, 5);
    k_t64split<<<(5 * 4096 + 255) / 256, 256>>>(nnW2, p_W2h, p_W2l, 5);
    k_tmlpB<<<(NL * 256 * 192 + 255) / 256, 256>>>(mlpW);
    k_tfc2<<<(Dd * OUTD + 255) / 256, 256>>>(fc2W);

    const int NBLIN = NnP / 64;

    k_lin64<false><<<NBLIN, 64>>>(x, p_encWt, encb, p_hB);

    for (int i = 0; i < NL; i++) {
        k_agg<<<(Nn * 32 + 255) / 256, 256>>>();
        k_layer<<<NBMMA, 384, L_SMEM_BYTES>>>(p_mlpBh + i * 49152, p_mlpBl + i * 49152,
                                              mlpb + i * Dd,
                                              p_W1h + i * 4096, p_W1l + i * 4096,
                                              p_W2h + i * 4096, p_W2l + i * 4096,
                                              nnb1 + i * Dd, nnb2 + i * Dd);
        k_bnfin<<<64, 256>>>(bnG + i * Dd, bnB + i * Dd);
    }

    k_bounds<<<(Gg + 1 + 255) / 256, 256>>>(batch);
    k_pool<<<Gg, 64>>>();
    k_head<<<Gg, 64>>>(fc1b, fc2b, out);
}

// round 15
// speedup vs baseline: 1.3005x; 1.1468x over previous
#include <cuda_runtime.h>
#include <cfloat>
#include <cstdint>

#define Nn 100000
#define NnP 100096          // multiple of 64
#define Ee 1600000
#define Dd 64
#define Gg 512
#define OUTD 16
#define NL 5
#define DELTA 2.5749f
#define BN_EPS 1e-5f
#define NB_L (NnP / 64)     // 1564 layer CTAs

// ---------------- static device scratch ----------------
static __device__ float g_hB[NnP * Dd];        // node features (pre-BN)
static __device__ float g_baseF[NnP * 256];    // [sum|max|mean|var] fp32
static __device__ float g_cfac[NnP];
static __device__ int   g_deg[Nn];
static __device__ int   g_sc[Nn];
static __device__ int   g_bsum[128];
static __device__ int   g_rowptr[Nn + 1];
static __device__ int   g_cursor[Nn];
static __device__ int   g_esrc[Ee];
static __device__ float g_part[NB_L * 128];    // per-CTA BN partials
static __device__ float g_scale[Dd];
static __device__ float g_shift[Dd];
static __device__ int   g_bstart[Gg + 1];
static __device__ float g_gpool[Gg * Dd];
static __device__ float g_encWt[Dd * Dd];
static __device__ float g_nnW1h[NL * Dd * Dd];  // [k][d] tf32 hi
static __device__ float g_nnW1l[NL * Dd * Dd];
static __device__ float g_nnW2h[NL * Dd * Dd];
static __device__ float g_nnW2l[NL * Dd * Dd];
static __device__ float g_mlpBh[NL * 256 * 192];  // [k][n], tf32 hi
static __device__ float g_mlpBl[NL * 256 * 192];
static __device__ float g_fc1Wt[Dd * Dd];
static __device__ float g_fc2Wt[Dd * OUTD];

__device__ __forceinline__ float tf32r(float x) {
    float y;
    asm("cvt.rna.tf32.f32 %0, %1;" : "=f"(y) : "f"(x));
    return y;
}
__device__ __forceinline__ void mma1688(float* c, const uint32_t* a, uint32_t b0, uint32_t b1) {
    asm volatile(
        "mma.sync.aligned.m16n8k8.row.col.f32.tf32.tf32.f32 "
        "{%0,%1,%2,%3}, {%4,%5,%6,%7}, {%8,%9}, {%0,%1,%2,%3};"
        : "+f"(c[0]), "+f"(c[1]), "+f"(c[2]), "+f"(c[3])
        : "r"(a[0]), "r"(a[1]), "r"(a[2]), "r"(a[3]), "r"(b0), "r"(b1));
}
__device__ __forceinline__ uint32_t smem_u32(const void* p) {
    uint32_t a;
    asm("{ .reg .u64 t; cvta.to.shared.u64 t, %1; cvt.u32.u64 %0, t; }" : "=r"(a) : "l"(p));
    return a;
}
__device__ __forceinline__ void cp16(uint32_t d, const void* s) {
    asm volatile("cp.async.cg.shared.global [%0], [%1], 16;" :: "r"(d), "l"(s));
}
#define CP_COMMIT() asm volatile("cp.async.commit_group;" ::: "memory")
#define CP_WAIT(n)  asm volatile("cp.async.wait_group %0;" :: "n"(n) : "memory")

// ---------------- CSR build ----------------
__global__ void k_zero_deg() {
    int i = blockIdx.x * blockDim.x + threadIdx.x;
    if (i < Nn) g_deg[i] = 0;
}
__global__ void k_count(const int* __restrict__ dst) {
    int e = blockIdx.x * blockDim.x + threadIdx.x;
    if (e < Ee) atomicAdd(&g_deg[dst[e]], 1);
}
__global__ void k_scan_block() {
    __shared__ int sm[1024];
    int i = blockIdx.x * 1024 + threadIdx.x;
    int v = (i < Nn) ? g_deg[i] : 0;
    sm[threadIdx.x] = v;
    __syncthreads();
    for (int off = 1; off < 1024; off <<= 1) {
        int t = 0;
        if (threadIdx.x >= off) t = sm[threadIdx.x - off];
        __syncthreads();
        sm[threadIdx.x] += t;
        __syncthreads();
    }
    if (i < Nn) g_sc[i] = sm[threadIdx.x];
    if (threadIdx.x == 1023) g_bsum[blockIdx.x] = sm[1023];
}
__global__ void k_scan_tops(int nb) {
    __shared__ int sm2[128];
    int t = threadIdx.x;
    int v = (t < nb) ? g_bsum[t] : 0;
    sm2[t] = v;
    __syncthreads();
    for (int off = 1; off < 128; off <<= 1) {
        int u = (t >= off) ? sm2[t - off] : 0;
        __syncthreads();
        sm2[t] += u;
        __syncthreads();
    }
    if (t < nb) g_bsum[t] = sm2[t] - v;
}
__global__ void k_rowptr() {
    int i = blockIdx.x * blockDim.x + threadIdx.x;
    if (i < Nn) {
        int rp = g_sc[i] - g_deg[i] + g_bsum[i >> 10];
        g_rowptr[i] = rp;
        g_cursor[i] = rp;
        g_cfac[i] = fmaxf((float)g_deg[i], 1.0f);
    }
    if (i == 0) g_rowptr[Nn] = Ee;
}
__global__ void k_scatter(const int* __restrict__ src, const int* __restrict__ dst) {
    int e = blockIdx.x * blockDim.x + threadIdx.x;
    if (e < Ee) {
        int p = atomicAdd(&g_cursor[dst[e]], 1);
        g_esrc[p] = src[e];
    }
}
__global__ void k_sortrows() {
    int n = blockIdx.x * blockDim.x + threadIdx.x;
    if (n >= Nn) return;
    int beg = g_rowptr[n], end = g_rowptr[n + 1];
    int deg = end - beg;
    if (deg <= 1) return;
    if (deg <= 64) {
        int buf[64];
        for (int i = 0; i < deg; i++) buf[i] = g_esrc[beg + i];
        for (int i = 1; i < deg; i++) {
            int v = buf[i];
            int j = i - 1;
            while (j >= 0 && buf[j] > v) { buf[j + 1] = buf[j]; j--; }
            buf[j + 1] = v;
        }
        for (int i = 0; i < deg; i++) g_esrc[beg + i] = buf[i];
    } else {
        for (int i = beg + 1; i < end; i++) {
            int v = g_esrc[i];
            int j = i - 1;
            while (j >= beg && g_esrc[j] > v) { g_esrc[j + 1] = g_esrc[j]; j--; }
            g_esrc[j + 1] = v;
        }
    }
}

// ---------------- weight prep ----------------
__global__ void k_t64(const float* __restrict__ W, float* __restrict__ Wt, int nm) {
    int idx = blockIdx.x * blockDim.x + threadIdx.x;
    if (idx >= nm * 4096) return;
    int m = idx >> 12, r = idx & 4095;
    int d = r >> 6, k = r & 63;
    Wt[(m << 12) + (k << 6) + d] = W[idx];
}
__global__ void k_t64split(const float* __restrict__ W, float* __restrict__ Wh,
                           float* __restrict__ Wl, int nm) {
    int idx = blockIdx.x * blockDim.x + threadIdx.x;
    if (idx >= nm * 4096) return;
    int m = idx >> 12, r = idx & 4095;
    int d = r >> 6, k = r & 63;
    float w = W[idx];
    float h = tf32r(w);
    Wh[(m << 12) + (k << 6) + d] = h;
    Wl[(m << 12) + (k << 6) + d] = tf32r(w - h);
}
__global__ void k_tmlpB(const float* __restrict__ W) {
    int idx = blockIdx.x * blockDim.x + threadIdx.x;
    if (idx >= NL * 256 * 192) return;
    int m = idx / 49152, r = idx % 49152;
    int k = r / 192, n = r % 192;
    int d = n & 63, b = n >> 6;
    float w = W[m * 49152 + d * 768 + b * 256 + k];
    float h = tf32r(w);
    g_mlpBh[idx] = h;
    g_mlpBl[idx] = tf32r(w - h);
}
// also initializes identity affine for layer 0
__global__ void k_tfc2(const float* __restrict__ W) {
    int idx = blockIdx.x * blockDim.x + threadIdx.x;
    if (idx < 64) { g_scale[idx] = 1.0f; g_shift[idx] = 0.0f; }
    if (idx >= Dd * OUTD) return;
    int o = idx >> 6, k = idx & 63;
    g_fc2Wt[k * 16 + o] = W[idx];
}

// ---------------- 64x64 linear (encoder only) ----------------
template <bool RELU>
__global__ void __launch_bounds__(64) k_lin64(const float* __restrict__ A,
                                              const float* __restrict__ Wt,
                                              const float* __restrict__ b,
                                              float* __restrict__ C) {
    __shared__ float4 Asm[64][16];
    int row0 = blockIdx.x * 64, tid = threadIdx.x;
    for (int t = tid; t < 1024; t += 64) {
        int r = t >> 4, c = t & 15;
        float4 v = make_float4(0.f, 0.f, 0.f, 0.f);
        if (row0 + r < Nn) v = ((const float4*)A)[(row0 + r) * 16 + c];
        Asm[r][c] = v;
    }
    __syncthreads();
    float acc[64];
#pragma unroll
    for (int r = 0; r < 64; r++) acc[r] = 0.f;
#pragma unroll 1
    for (int k4 = 0; k4 < 16; k4++) {
        float w0 = Wt[(k4 * 4 + 0) * 64 + tid];
        float w1 = Wt[(k4 * 4 + 1) * 64 + tid];
        float w2 = Wt[(k4 * 4 + 2) * 64 + tid];
        float w3 = Wt[(k4 * 4 + 3) * 64 + tid];
#pragma unroll
        for (int r = 0; r < 64; r++) {
            float4 a = Asm[r][k4];
            float t0 = fmaf(a.x, w0, acc[r]);
            t0 = fmaf(a.y, w1, t0);
            t0 = fmaf(a.z, w2, t0);
            acc[r] = fmaf(a.w, w3, t0);
        }
    }
    float bb = b[tid];
    for (int r = 0; r < 64; r++) {
        if (row0 + r < Nn) {
            float v = acc[r] + bb;
            if (RELU) v = fmaxf(v, 0.f);
            C[(row0 + r) * 64 + tid] = v;
        }
    }
}

// ---------------- PNA aggregation (warp/node, affine on the fly, 4-way unroll) ----------------
__global__ void k_agg() {
    int gt = blockIdx.x * blockDim.x + threadIdx.x;
    int w = gt >> 5, lane = gt & 31;
    if (w >= Nn) return;
    int beg = g_rowptr[w], end = g_rowptr[w + 1];
    const float2* hp = (const float2*)g_hB;
    float scx = g_scale[2 * lane], scy = g_scale[2 * lane + 1];
    float shx = g_shift[2 * lane], shy = g_shift[2 * lane + 1];
    float sxA = 0.f, syA = 0.f, qxA = 0.f, qyA = 0.f;
    float sxB = 0.f, syB = 0.f, qxB = 0.f, qyB = 0.f;
    float mxx = -FLT_MAX, mxy = -FLT_MAX;
    int j = beg;
    for (; j + 3 < end; j += 4) {
        int s0 = g_esrc[j];
        int s1 = g_esrc[j + 1];
        int s2 = g_esrc[j + 2];
        int s3 = g_esrc[j + 3];
        float2 r0 = hp[s0 * 32 + lane];
        float2 r1 = hp[s1 * 32 + lane];
        float2 r2 = hp[s2 * 32 + lane];
        float2 r3 = hp[s3 * 32 + lane];
        float v0x = fmaf(r0.x, scx, shx), v0y = fmaf(r0.y, scy, shy);
        float v1x = fmaf(r1.x, scx, shx), v1y = fmaf(r1.y, scy, shy);
        float v2x = fmaf(r2.x, scx, shx), v2y = fmaf(r2.y, scy, shy);
        float v3x = fmaf(r3.x, scx, shx), v3y = fmaf(r3.y, scy, shy);
        sxA += v0x; syA += v0y;
        qxA = fmaf(v0x, v0x, qxA); qyA = fmaf(v0y, v0y, qyA);
        mxx = fmaxf(mxx, v0x); mxy = fmaxf(mxy, v0y);
        sxB += v1x; syB += v1y;
        qxB = fmaf(v1x, v1x, qxB); qyB = fmaf(v1y, v1y, qyB);
        mxx = fmaxf(mxx, v1x); mxy = fmaxf(mxy, v1y);
        sxA += v2x; syA += v2y;
        qxA = fmaf(v2x, v2x, qxA); qyA = fmaf(v2y, v2y, qyA);
        mxx = fmaxf(mxx, v2x); mxy = fmaxf(mxy, v2y);
        sxB += v3x; syB += v3y;
        qxB = fmaf(v3x, v3x, qxB); qyB = fmaf(v3y, v3y, qyB);
        mxx = fmaxf(mxx, v3x); mxy = fmaxf(mxy, v3y);
    }
    for (; j < end; j++) {
        int s0 = g_esrc[j];
        float2 r0 = hp[s0 * 32 + lane];
        float v0x = fmaf(r0.x, scx, shx), v0y = fmaf(r0.y, scy, shy);
        sxA += v0x; syA += v0y;
        qxA = fmaf(v0x, v0x, qxA); qyA = fmaf(v0y, v0y, qyA);
        mxx = fmaxf(mxx, v0x); mxy = fmaxf(mxy, v0y);
    }
    float sx = sxA + sxB, sy = syA + syB;
    float qx = qxA + qxB, qy = qyA + qyB;
    if (end == beg) { mxx = 0.f; mxy = 0.f; }
    float c = g_cfac[w];
    float inv = 1.f / c;
    float mex = sx * inv, mey = sy * inv;
    float vx = fmaxf(qx * inv - mex * mex, 0.f);
    float vy = fmaxf(qy * inv - mey * mey, 0.f);
    float2* bp = (float2*)(g_baseF + (size_t)w * 256);
    bp[lane]      = make_float2(sx, sy);
    bp[32 + lane] = make_float2(mxx, mxy);
    bp[64 + lane] = make_float2(mex, mey);
    bp[96 + lane] = make_float2(vx, vy);
}

// ---------------- merged layer kernel: 64-row CTA, 2 CTAs/SM ----------------
// phase 1: pipelined 3xTF32 GEMM S = base @ B  (12 warps: 4m(16 rows) x 3n(64 cols))
// phase 2: stage S into R + prefetch W1; combine -> frags aliasing R seg0/seg1
// phase 3: nn stage1/stage2 (warps 0-7: 4m x 2n), W2 prefetched under resplit
// phase 4: epilogue writes g_hB + deterministic BN partials
#define A_STRIDE 20
#define BS_STRIDE 200
#define R_STRIDE 204
#define BH_OFF 1280
#define BL_OFF 4480
#define STG 7680                          // floats per stage (A 1280 + B 2x3200)
#define W_OFF  13056                      // after R (64*204)
#define WL_OFF 17664
#define L_FLOATS 22272
#define L_SMEM_BYTES (L_FLOATS * 4)       // 89088

__global__ void __launch_bounds__(384, 2)
k_layer(const float* __restrict__ Bh, const float* __restrict__ Bl,
        const float* __restrict__ mb,
        const float* __restrict__ W1h, const float* __restrict__ W1l,
        const float* __restrict__ W2h, const float* __restrict__ W2l,
        const float* __restrict__ b1, const float* __restrict__ b2) {
    extern __shared__ float sm[];
    uint32_t sb = smem_u32(sm);
    int tid = threadIdx.x, wid = tid >> 5, lane = tid & 31;
    int gid = lane >> 2, tig = lane & 3;
    int row0 = blockIdx.x * 64;
    int mrow0 = (wid & 3) * 16;
    int ncol0p = (wid >> 2) * 64;   // pna n offset (12 warps: 4m x 3n)
    int ncol0f = (wid >> 2) * 32;   // nn n offset (warps 0-7: 4m x 2n)

    // async load of one K=16 chunk (A fp32 + B hi/lo) into buffer `buf`
    auto load_stage = [&](int kc, int buf) {
        uint32_t base = sb + (uint32_t)(buf * STG) * 4;
        for (int i = tid; i < 256; i += 384) {
            int r = i >> 2, c4 = i & 3;
            cp16(base + (uint32_t)(r * A_STRIDE + c4 * 4) * 4,
                 &g_baseF[(size_t)(row0 + r) * 256 + kc * 16 + c4 * 4]);
        }
        uint32_t bH = base + BH_OFF * 4;
        uint32_t bL = base + BL_OFF * 4;
        for (int i = tid; i < 768; i += 384) {
            int r = i / 48, c4 = i % 48;
            uint32_t off = (uint32_t)(r * BS_STRIDE + c4 * 4) * 4;
            size_t go = (size_t)(kc * 16 + r) * 192 + c4 * 4;
            cp16(bH + off, &Bh[go]);
            cp16(bL + off, &Bl[go]);
        }
    };

    float acc[8][4];
#pragma unroll
    for (int nt = 0; nt < 8; nt++)
#pragma unroll
        for (int j = 0; j < 4; j++) acc[nt][j] = 0.f;

    load_stage(0, 0);
    CP_COMMIT();
    load_stage(1, 1);
    CP_COMMIT();

#pragma unroll 1
    for (int kc = 0; kc < 16; kc++) {
        if (kc == 15) { CP_WAIT(0); } else { CP_WAIT(1); }
        __syncthreads();
        const float* As  = sm + (kc & 1) * STG;
        const float* Bsh = As + BH_OFF;
        const float* Bsl = As + BL_OFF;
#pragma unroll
        for (int k8 = 0; k8 < 2; k8++) {
            int kb = k8 * 8;
            int mr = mrow0 + gid;
            float a0 = As[mr * A_STRIDE + kb + tig];
            float a1 = As[(mr + 8) * A_STRIDE + kb + tig];
            float a2 = As[mr * A_STRIDE + kb + tig + 4];
            float a3 = As[(mr + 8) * A_STRIDE + kb + tig + 4];
            float h0 = tf32r(a0), h1 = tf32r(a1), h2 = tf32r(a2), h3 = tf32r(a3);
            uint32_t ah[4], al[4];
            ah[0] = __float_as_uint(h0);
            ah[1] = __float_as_uint(h1);
            ah[2] = __float_as_uint(h2);
            ah[3] = __float_as_uint(h3);
            al[0] = __float_as_uint(tf32r(a0 - h0));
            al[1] = __float_as_uint(tf32r(a1 - h1));
            al[2] = __float_as_uint(tf32r(a2 - h2));
            al[3] = __float_as_uint(tf32r(a3 - h3));
#pragma unroll
            for (int nt = 0; nt < 8; nt++) {
                int nc = ncol0p + nt * 8 + gid;
                uint32_t bh0 = __float_as_uint(Bsh[(kb + tig) * BS_STRIDE + nc]);
                uint32_t bh1 = __float_as_uint(Bsh[(kb + tig + 4) * BS_STRIDE + nc]);
                uint32_t bl0 = __float_as_uint(Bsl[(kb + tig) * BS_STRIDE + nc]);
                uint32_t bl1 = __float_as_uint(Bsl[(kb + tig + 4) * BS_STRIDE + nc]);
                mma1688(acc[nt], ah, bh0, bh1);
                mma1688(acc[nt], ah, bl0, bl1);
                mma1688(acc[nt], al, bh0, bh1);
            }
        }
        __syncthreads();
        if (kc + 2 < 16) {
            load_stage(kc + 2, kc & 1);
            CP_COMMIT();
        }
    }

    // ---- phase 2: prefetch W1 (disjoint region), stage S into R, combine ----
    {
        uint32_t whA = sb + W_OFF * 4, wlA = sb + WL_OFF * 4;
        for (int i = tid; i < 2048; i += 384) {
            int c = i & 1023;
            int k = c >> 4, c4 = c & 15;
            uint32_t off = (uint32_t)(k * 72 + c4 * 4) * 4;
            if (i < 1024) cp16(whA + off, &W1h[c * 4]);
            else          cp16(wlA + off, &W1l[c * 4]);
        }
        CP_COMMIT();
    }
#pragma unroll
    for (int nt = 0; nt < 8; nt++) {
        int r = mrow0 + gid;
        int c = ncol0p + nt * 8 + tig * 2;
        *(float2*)&sm[r * R_STRIDE + c] = make_float2(acc[nt][0], acc[nt][1]);
        *(float2*)&sm[(r + 8) * R_STRIDE + c] = make_float2(acc[nt][2], acc[nt][3]);
    }
    __syncthreads();

    // combine: u = affine(hB) + mb + S0 + (c/D)S1 + (D/c)S2; frags alias R seg0/seg1
    for (int i = tid; i < 64 * 64; i += 384) {
        int r = i >> 6, d = i & 63;
        int row = row0 + r;
        float h = 0.f, l = 0.f;
        float* Rr = sm + r * R_STRIDE;
        if (row < Nn) {
            float cf = g_cfac[row];
            float aa = cf * (1.0f / DELTA);
            float b2c = DELTA / cf;
            float x = fmaf(g_hB[(size_t)row * 64 + d], g_scale[d], g_shift[d]);
            float v = x + mb[d] + Rr[d] + aa * Rr[64 + d] + b2c * Rr[128 + d];
            h = tf32r(v);
            l = tf32r(v - h);
        }
        Rr[d] = h;        // overwrite S0 slot (same-thread exclusive)
        Rr[64 + d] = l;   // overwrite S1 slot
    }
    CP_WAIT(0);
    __syncthreads();

    // ---- phase 3: nn stage 1 (warps 0-7) ----
    float acc2[4][4];
    const float* wh = sm + W_OFF;
    const float* wl = sm + WL_OFF;
    if (wid < 8) {
#pragma unroll
        for (int nt = 0; nt < 4; nt++)
#pragma unroll
            for (int j = 0; j < 4; j++) acc2[nt][j] = 0.f;
#pragma unroll 1
        for (int k8 = 0; k8 < 8; k8++) {
            int kb = k8 * 8;
            int mr = mrow0 + gid;
            uint32_t ah[4], al[4];
            ah[0] = __float_as_uint(sm[mr * R_STRIDE + kb + tig]);
            ah[1] = __float_as_uint(sm[(mr + 8) * R_STRIDE + kb + tig]);
            ah[2] = __float_as_uint(sm[mr * R_STRIDE + kb + tig + 4]);
            ah[3] = __float_as_uint(sm[(mr + 8) * R_STRIDE + kb + tig + 4]);
            al[0] = __float_as_uint(sm[mr * R_STRIDE + 64 + kb + tig]);
            al[1] = __float_as_uint(sm[(mr + 8) * R_STRIDE + 64 + kb + tig]);
            al[2] = __float_as_uint(sm[mr * R_STRIDE + 64 + kb + tig + 4]);
            al[3] = __float_as_uint(sm[(mr + 8) * R_STRIDE + 64 + kb + tig + 4]);
#pragma unroll
            for (int nt = 0; nt < 4; nt++) {
                int nc = ncol0f + nt * 8 + gid;
                uint32_t bh0 = __float_as_uint(wh[(kb + tig) * 72 + nc]);
                uint32_t bh1 = __float_as_uint(wh[(kb + tig + 4) * 72 + nc]);
                uint32_t bl0 = __float_as_uint(wl[(kb + tig) * 72 + nc]);
                uint32_t bl1 = __float_as_uint(wl[(kb + tig + 4) * 72 + nc]);
                mma1688(acc2[nt], ah, bh0, bh1);
                mma1688(acc2[nt], ah, bl0, bl1);
                mma1688(acc2[nt], al, bh0, bh1);
            }
        }
    }
    __syncthreads();   // all reads of W1 + frags done

    // async load W2; hide under relu-resplit
    {
        uint32_t whA = sb + W_OFF * 4, wlA = sb + WL_OFF * 4;
        for (int i = tid; i < 2048; i += 384) {
            int c = i & 1023;
            int k = c >> 4, c4 = c & 15;
            uint32_t off = (uint32_t)(k * 72 + c4 * 4) * 4;
            if (i < 1024) cp16(whA + off, &W2h[c * 4]);
            else          cp16(wlA + off, &W2l[c * 4]);
        }
        CP_COMMIT();
    }
    if (wid < 8) {
#pragma unroll
        for (int nt = 0; nt < 4; nt++) {
            int r = mrow0 + gid;
            int c = ncol0f + nt * 8 + tig * 2;
            float bb0 = b1[c], bb1 = b1[c + 1];
            float u0 = fmaxf(acc2[nt][0] + bb0, 0.f);
            float u1 = fmaxf(acc2[nt][1] + bb1, 0.f);
            float u2 = fmaxf(acc2[nt][2] + bb0, 0.f);
            float u3 = fmaxf(acc2[nt][3] + bb1, 0.f);
            float h0 = tf32r(u0), h1 = tf32r(u1), h2 = tf32r(u2), h3 = tf32r(u3);
            sm[r * R_STRIDE + c] = h0;
            sm[r * R_STRIDE + c + 1] = h1;
            sm[(r + 8) * R_STRIDE + c] = h2;
            sm[(r + 8) * R_STRIDE + c + 1] = h3;
            sm[r * R_STRIDE + 64 + c] = tf32r(u0 - h0);
            sm[r * R_STRIDE + 64 + c + 1] = tf32r(u1 - h1);
            sm[(r + 8) * R_STRIDE + 64 + c] = tf32r(u2 - h2);
            sm[(r + 8) * R_STRIDE + 64 + c + 1] = tf32r(u3 - h3);
        }
    }
    CP_WAIT(0);
    __syncthreads();

    // ---- nn stage 2 ----
    if (wid < 8) {
#pragma unroll
        for (int nt = 0; nt < 4; nt++)
#pragma unroll
            for (int j = 0; j < 4; j++) acc2[nt][j] = 0.f;
#pragma unroll 1
        for (int k8 = 0; k8 < 8; k8++) {
            int kb = k8 * 8;
            int mr = mrow0 + gid;
            uint32_t ah[4], al[4];
            ah[0] = __float_as_uint(sm[mr * R_STRIDE + kb + tig]);
            ah[1] = __float_as_uint(sm[(mr + 8) * R_STRIDE + kb + tig]);
            ah[2] = __float_as_uint(sm[mr * R_STRIDE + kb + tig + 4]);
            ah[3] = __float_as_uint(sm[(mr + 8) * R_STRIDE + kb + tig + 4]);
            al[0] = __float_as_uint(sm[mr * R_STRIDE + 64 + kb + tig]);
            al[1] = __float_as_uint(sm[(mr + 8) * R_STRIDE + 64 + kb + tig]);
            al[2] = __float_as_uint(sm[mr * R_STRIDE + 64 + kb + tig + 4]);
            al[3] = __float_as_uint(sm[(mr + 8) * R_STRIDE + 64 + kb + tig + 4]);
#pragma unroll
            for (int nt = 0; nt < 4; nt++) {
                int nc = ncol0f + nt * 8 + gid;
                uint32_t bh0 = __float_as_uint(wh[(kb + tig) * 72 + nc]);
                uint32_t bh1 = __float_as_uint(wh[(kb + tig + 4) * 72 + nc]);
                uint32_t bl0 = __float_as_uint(wl[(kb + tig) * 72 + nc]);
                uint32_t bl1 = __float_as_uint(wl[(kb + tig + 4) * 72 + nc]);
                mma1688(acc2[nt], ah, bh0, bh1);
                mma1688(acc2[nt], ah, bl0, bl1);
                mma1688(acc2[nt], al, bh0, bh1);
            }
        }
    }
    __syncthreads();   // frags free for output staging

    // ---- phase 4: epilogue (outer relu) + BN staging ----
    if (wid < 8) {
#pragma unroll
        for (int nt = 0; nt < 4; nt++) {
            int r = mrow0 + gid;
            int c = ncol0f + nt * 8 + tig * 2;
            float bb0 = b2[c], bb1 = b2[c + 1];
            int row = row0 + r;
            float v0 = fmaxf(acc2[nt][0] + bb0, 0.f);
            float v1 = fmaxf(acc2[nt][1] + bb1, 0.f);
            float v2 = fmaxf(acc2[nt][2] + bb0, 0.f);
            float v3 = fmaxf(acc2[nt][3] + bb1, 0.f);
            if (row < Nn) {
                *(float2*)&g_hB[(size_t)row * 64 + c] = make_float2(v0, v1);
            } else { v0 = 0.f; v1 = 0.f; }
            if (row + 8 < Nn) {
                *(float2*)&g_hB[(size_t)(row + 8) * 64 + c] = make_float2(v2, v3);
            } else { v2 = 0.f; v3 = 0.f; }
            sm[r * R_STRIDE + c] = v0;
            sm[r * R_STRIDE + c + 1] = v1;
            sm[(r + 8) * R_STRIDE + c] = v2;
            sm[(r + 8) * R_STRIDE + c + 1] = v3;
        }
    }
    __syncthreads();

    if (tid < 128) {
        int f = tid & 63;
        bool sq = tid >= 64;
        float s = 0.f;
#pragma unroll 4
        for (int r = 0; r < 64; r++) {
            float v = sm[r * R_STRIDE + f];
            s += sq ? v * v : v;
        }
        g_part[blockIdx.x * 128 + tid] = s;
    }
}

// ---------------- BN finalize: grid=64 (one CTA per feature) ----------------
__global__ void __launch_bounds__(256)
k_bnfin(const float* __restrict__ gamma, const float* __restrict__ beta) {
    __shared__ float red[512];
    int f = blockIdx.x, tid = threadIdx.x;
    float s = 0.f, q = 0.f;
    for (int c = tid; c < NB_L; c += 256) {
        s += g_part[c * 128 + f];
        q += g_part[c * 128 + 64 + f];
    }
    red[tid] = s;
    red[256 + tid] = q;
    __syncthreads();
    for (int off = 128; off > 0; off >>= 1) {
        if (tid < off) {
            red[tid] += red[tid + off];
            red[256 + tid] += red[256 + tid + off];
        }
        __syncthreads();
    }
    if (tid == 0) {
        float mean = red[0] * (1.0f / Nn);
        float var = red[256] * (1.0f / Nn) - mean * mean;
        float sc = gamma[f] * rsqrtf(var + BN_EPS);
        g_scale[f] = sc;
        g_shift[f] = fmaf(-mean, sc, beta[f]);
    }
}

// ---------------- pooling + head ----------------
__global__ void k_bounds(const int* __restrict__ batch) {
    int g = blockIdx.x * blockDim.x + threadIdx.x;
    if (g > Gg) return;
    if (g == Gg) { g_bstart[Gg] = Nn; return; }
    int lo = 0, hi = Nn;
    while (lo < hi) {
        int mid = (lo + hi) >> 1;
        if (batch[mid] < g) lo = mid + 1; else hi = mid;
    }
    g_bstart[g] = lo;
}
__global__ void k_pool() {
    int g = blockIdx.x, d = threadIdx.x;
    int r0 = g_bstart[g], r1 = g_bstart[g + 1];
    float sc = g_scale[d], sh = g_shift[d];
    float s = 0.f;
    for (int r = r0; r < r1; r++) s += fmaf(g_hB[r * 64 + d], sc, sh);
    g_gpool[g * 64 + d] = s;
}
__global__ void k_head(const float* __restrict__ fc1b, const float* __restrict__ fc2b,
                       float* __restrict__ out) {
    __shared__ float gsm[64], tsm[64];
    int g = blockIdx.x, d = threadIdx.x;
    gsm[d] = g_gpool[g * 64 + d];
    __syncthreads();
    float acc = fc1b[d];
    for (int k = 0; k < 64; k++) acc = fmaf(gsm[k], g_fc1Wt[k * 64 + d], acc);
    tsm[d] = fmaxf(acc, 0.f);
    __syncthreads();
    if (d < OUTD) {
        float a2 = fc2b[d];
        for (int k = 0; k < 64; k++) a2 = fmaf(tsm[k], g_fc2Wt[k * 16 + d], a2);
        out[g * OUTD + d] = a2;
    }
}

// ---------------- host ----------------
extern "C" void kernel_launch(void* const* d_in, const int* in_sizes, int n_in,
                              void* d_out, int out_size) {
    const float* x    = (const float*)d_in[0];
    const int*   ei   = (const int*)d_in[1];
    const int*   src  = ei;
    const int*   dst  = ei + Ee;
    const int*   batch = (const int*)d_in[2];
    const float* encW = (const float*)d_in[3];
    const float* encb = (const float*)d_in[4];
    const float* nnW1 = (const float*)d_in[5];
    const float* nnb1 = (const float*)d_in[6];
    const float* nnW2 = (const float*)d_in[7];
    const float* nnb2 = (const float*)d_in[8];
    const float* mlpW = (const float*)d_in[9];
    const float* mlpb = (const float*)d_in[10];
    const float* bnG  = (const float*)d_in[11];
    const float* bnB  = (const float*)d_in[12];
    const float* fc1W = (const float*)d_in[13];
    const float* fc1b = (const float*)d_in[14];
    const float* fc2W = (const float*)d_in[15];
    const float* fc2b = (const float*)d_in[16];
    float* out = (float*)d_out;

    float *p_hB, *p_encWt, *p_fc1Wt, *p_mlpBh, *p_mlpBl;
    float *p_W1h, *p_W1l, *p_W2h, *p_W2l;
    cudaGetSymbolAddress((void**)&p_hB, g_hB);
    cudaGetSymbolAddress((void**)&p_encWt, g_encWt);
    cudaGetSymbolAddress((void**)&p_fc1Wt, g_fc1Wt);
    cudaGetSymbolAddress((void**)&p_mlpBh, g_mlpBh);
    cudaGetSymbolAddress((void**)&p_mlpBl, g_mlpBl);
    cudaGetSymbolAddress((void**)&p_W1h, g_nnW1h);
    cudaGetSymbolAddress((void**)&p_W1l, g_nnW1l);
    cudaGetSymbolAddress((void**)&p_W2h, g_nnW2h);
    cudaGetSymbolAddress((void**)&p_W2l, g_nnW2l);

    cudaFuncSetAttribute(k_layer, cudaFuncAttributeMaxDynamicSharedMemorySize, L_SMEM_BYTES);

    const int NB_SCAN = (Nn + 1023) / 1024;

    // CSR build
    k_zero_deg<<<(Nn + 255) / 256, 256>>>();
    k_count<<<(Ee + 255) / 256, 256>>>(dst);
    k_scan_block<<<NB_SCAN, 1024>>>();
    k_scan_tops<<<1, 128>>>(NB_SCAN);
    k_rowptr<<<(Nn + 255) / 256, 256>>>();
    k_scatter<<<(Ee + 255) / 256, 256>>>(src, dst);
    k_sortrows<<<(Nn + 255) / 256, 256>>>();

    // weight prep (k_tfc2 also sets identity affine for layer 0)
    k_t64<<<(4096 + 255) / 256, 256>>>(encW, p_encWt, 1);
    k_t64<<<(4096 + 255) / 256, 256>>>(fc1W, p_fc1Wt, 1);
    k_t64split<<<(5 * 4096 + 255) / 256, 256>>>(nnW1, p_W1h, p_W1l, 5);
    k_t64split<<<(5 * 4096 + 255) / 256, 256>>>(nnW2, p_W2h, p_W2l, 5);
    k_tmlpB<<<(NL * 256 * 192 + 255) / 256, 256>>>(mlpW);
    k_tfc2<<<(Dd * OUTD + 255) / 256, 256>>>(fc2W);

    const int NBLIN = NnP / 64;

    k_lin64<false><<<NBLIN, 64>>>(x, p_encWt, encb, p_hB);

    for (int i = 0; i < NL; i++) {
        k_agg<<<(Nn * 32 + 255) / 256, 256>>>();
        k_layer<<<NB_L, 384, L_SMEM_BYTES>>>(p_mlpBh + i * 49152, p_mlpBl + i * 49152,
                                             mlpb + i * Dd,
                                             p_W1h + i * 4096, p_W1l + i * 4096,
                                             p_W2h + i * 4096, p_W2l + i * 4096,
                                             nnb1 + i * Dd, nnb2 + i * Dd);
        k_bnfin<<<64, 256>>>(bnG + i * Dd, bnB + i * Dd);
    }

    k_bounds<<<(Gg + 1 + 255) / 256, 256>>>(batch);
    k_pool<<<Gg, 64>>>();
    k_head<<<Gg, 64>>>(fc1b, fc2b, out);
}